// round 3
// baseline (speedup 1.0000x reference)
#include <cuda_runtime.h>
#include <cstdint>

typedef unsigned long long ull;

// ---------------------------------------------------------------------------
// Problem constants (fixed by setup_inputs: B=4, C=32, H=W=128, scale=2)
// ---------------------------------------------------------------------------
#define Bn    4
#define Cn    32
#define Hn    128
#define Wn    128
#define QPB   65536                // 256*256 queries per image
#define NQ    (Bn * QPB)
#define MTILE 64                   // queries per CTA
#define NCTA  (NQ / MTILE)         // 4096
#define STR   68                   // padded row stride (floats), 16B-aligned

// channels-last copy of x: [B, H, W, C]
__device__ float g_xt[Bn * Hn * Wn * Cn];

// ---------------------------------------------------------------------------
// Transpose kernel: x[B,C,H,W] -> g_xt[B,H,W,C]
// ---------------------------------------------------------------------------
__global__ void xt_kernel(const float* __restrict__ x) {
    __shared__ float s[Cn][Wn + 1];
    const int by = blockIdx.x;          // b*128 + y
    const int tid = threadIdx.x;        // 256 threads
#pragma unroll
    for (int it = 0; it < 16; ++it) {
        int idx = tid + it * 256;
        int c = idx >> 7;
        int xc = idx & 127;
        int b = by >> 7, y = by & 127;
        s[c][xc] = x[((b * Cn + c) * Hn + y) * Wn + xc];
    }
    __syncthreads();
#pragma unroll
    for (int it = 0; it < 16; ++it) {
        int idx = tid + it * 256;
        int xc = idx >> 5;
        int c = idx & 31;
        g_xt[(by * Wn + xc) * Cn + c] = s[c][xc];
    }
}

// ---------------------------------------------------------------------------
// Packed f32x2 helpers (sm_103a full-rate dual FMA; ptxas never auto-emits)
// ---------------------------------------------------------------------------
__device__ __forceinline__ ull ffma2(ull a, ull b, ull c) {
    ull d;
    asm("fma.rn.f32x2 %0, %1, %2, %3;" : "=l"(d) : "l"(a), "l"(b), "l"(c));
    return d;
}
__device__ __forceinline__ ull rep2(float a) {
    ull d;
    asm("mov.b64 %0, {%1, %1};" : "=l"(d) : "f"(a));
    return d;
}
__device__ __forceinline__ float2 unpack2(ull v) {
    float2 r;
    asm("mov.b64 {%0, %1}, %2;" : "=f"(r.x), "=f"(r.y) : "l"(v));
    return r;
}

// ---------------------------------------------------------------------------
// Bicubic helpers (torch aten formulation, A = -0.75)
// ---------------------------------------------------------------------------
__device__ __forceinline__ void prep_axis(float g, int& i0, float w[4]) {
    float p = ((g + 1.0f) * 128.0f - 1.0f) * 0.5f;
    float fp = floorf(p);
    i0 = (int)fp;
    float t = p - fp;
    const float A = -0.75f;
    float xx = t + 1.0f;
    w[0] = ((A * xx - 5.0f * A) * xx + 8.0f * A) * xx - 4.0f * A;
    w[1] = ((A + 2.0f) * t - (A + 3.0f)) * t * t + 1.0f;
    float s = 1.0f - t;
    w[2] = ((A + 2.0f) * s - (A + 3.0f)) * s * s + 1.0f;
    w[3] = 1.0f - w[0] - w[1] - w[2];
}

__device__ __forceinline__ float sample_c(const float* __restrict__ xb, int lane,
                                          int ix0, int iy0,
                                          const float* wx, const float* wy) {
    float acc = 0.0f;
#pragma unroll
    for (int i = 0; i < 4; ++i) {
        int yi = iy0 - 1 + i;
        if ((unsigned)yi < 128u) {
            const float* rp = xb + yi * (Wn * Cn) + lane;
            float r = 0.0f;
#pragma unroll
            for (int j = 0; j < 4; ++j) {
                int xj = ix0 - 1 + j;
                if ((unsigned)xj < 128u) r = fmaf(wx[j], __ldg(rp + xj * Cn), r);
            }
            acc = fmaf(wy[i], r, acc);
        }
    }
    return acc;
}

// ---------------------------------------------------------------------------
// Shared-memory GEMM tile with f32x2 packed math.
//   in   : smem [K][STR] (queries m along the row)
//   w    : global row-major [K][N]
//   outT : smem [N][STR]   (may alias `in` — internal sync before writes)
//
// N>=256 layers: thread tile 8 M x 8 N (4 f32x2 pairs).
//   warp = 8 M-groups x 4 N-groups; 8 warps cover N=256.
//   per k: 2 LDS.128 (acts) + 2 LDG.128 (weights) + 8 rep2 + 32 FFMA2.
// N==32 layers: thread tile 4 M x 2 N (1 pair), warp = 16 M x 2 N groups.
// ---------------------------------------------------------------------------
template <int K, int N, bool RELU>
__device__ __forceinline__ void gemm_tile(const float* __restrict__ in,
                                          const float* __restrict__ w,
                                          const float* __restrict__ bias,
                                          float* __restrict__ outT) {
    const int lane = threadIdx.x & 31;
    const int wid  = threadIdx.x >> 5;
    constexpr int NW = N / 8;                   // columns per warp
    constexpr bool BIG = (N >= 256);
    constexpr int MT = BIG ? 8 : 4;             // M rows per thread
    constexpr int NT = BIG ? 8 : 2;             // N cols per thread
    constexpr int NP = NT / 2;                  // f32x2 pairs per thread
    const int m0 = BIG ? (lane & 7) * 8 : (lane & 15) * 4;
    const int n0 = wid * NW + (BIG ? (lane >> 3) : (lane >> 4)) * NT;

    ull acc[MT][NP];
#pragma unroll
    for (int mi = 0; mi < MT; ++mi)
#pragma unroll
        for (int p = 0; p < NP; ++p) acc[mi][p] = 0ull;

    const float* ip = in + m0;
    const float* wp = w + n0;
#pragma unroll 2
    for (int k = 0; k < K; ++k) {
        // activations: MT consecutive queries
        float av[MT];
        {
            float4 a0 = *reinterpret_cast<const float4*>(ip + k * STR);
            av[0] = a0.x; av[1] = a0.y; av[2] = a0.z; av[3] = a0.w;
            if constexpr (MT == 8) {
                float4 a1 = *reinterpret_cast<const float4*>(ip + k * STR + 4);
                av[4] = a1.x; av[5] = a1.y; av[6] = a1.z; av[7] = a1.w;
            }
        }
        ull ar[MT];
#pragma unroll
        for (int mi = 0; mi < MT; ++mi) ar[mi] = rep2(av[mi]);

        ull wr[NP];
        if constexpr (NP >= 2) {
#pragma unroll
            for (int q = 0; q < NP / 2; ++q) {
                ulonglong2 wv = __ldg(
                    reinterpret_cast<const ulonglong2*>(wp + k * N + q * 4));
                wr[2 * q]     = wv.x;
                wr[2 * q + 1] = wv.y;
            }
        } else {
            wr[0] = __ldg(reinterpret_cast<const ull*>(wp + k * N));
        }
#pragma unroll
        for (int mi = 0; mi < MT; ++mi)
#pragma unroll
            for (int p = 0; p < NP; ++p)
                acc[mi][p] = ffma2(ar[mi], wr[p], acc[mi][p]);
    }

    __syncthreads();   // all reads of `in` done -> safe to alias outT with in

#pragma unroll
    for (int p = 0; p < NP; ++p) {
        float bz0 = __ldg(bias + n0 + 2 * p);
        float bz1 = __ldg(bias + n0 + 2 * p + 1);
        float c0[MT], c1[MT];
#pragma unroll
        for (int mi = 0; mi < MT; ++mi) {
            float2 u = unpack2(acc[mi][p]);
            float v0 = u.x + bz0;
            float v1 = u.y + bz1;
            if (RELU) { v0 = fmaxf(v0, 0.f); v1 = fmaxf(v1, 0.f); }
            c0[mi] = v0; c1[mi] = v1;
        }
        float* o0 = outT + (n0 + 2 * p) * STR + m0;
        float* o1 = outT + (n0 + 2 * p + 1) * STR + m0;
#pragma unroll
        for (int j = 0; j < MT / 4; ++j) {
            *reinterpret_cast<float4*>(o0 + 4 * j) =
                make_float4(c0[4 * j], c0[4 * j + 1], c0[4 * j + 2], c0[4 * j + 3]);
            *reinterpret_cast<float4*>(o1 + 4 * j) =
                make_float4(c1[4 * j], c1[4 * j + 1], c1[4 * j + 2], c1[4 * j + 3]);
        }
    }
}

// ---------------------------------------------------------------------------
// Fused main kernel: one CTA = 64 consecutive queries of one batch image.
// smem ~97 KB -> 2 CTAs/SM.
// ---------------------------------------------------------------------------
#define SMEM_FLOATS ((36 + 256 + 32 + 32) * STR + 128)
#define SMEM_BYTES  (SMEM_FLOATS * 4)

__global__ __launch_bounds__(256, 2) void fused_kernel(
    const float* __restrict__ w0, const float* __restrict__ b0,
    const float* __restrict__ w1, const float* __restrict__ b1,
    const float* __restrict__ w2, const float* __restrict__ b2,
    const float* __restrict__ rw0, const float* __restrict__ rb0,
    const float* __restrict__ rw1, const float* __restrict__ rb1,
    const float* __restrict__ ow0, const float* __restrict__ ob0,
    const float* __restrict__ ow1, const float* __restrict__ ob1,
    float* __restrict__ out) {
    extern __shared__ float sm[];
    float* inpT  = sm;                       // [36][STR]  (reused as out stage)
    float* bufA  = inpT + 36 * STR;          // [256][STR] (in-place reused)
    float* predT = bufA + 256 * STR;         // [32][STR]
    float* routT = predT + 32 * STR;         // [32][STR]
    float* offs  = routT + 32 * STR;         // [64][2]

    const int tid = threadIdx.x;
    const int lane = tid & 31;
    const int wid = tid >> 5;
    const int q0 = blockIdx.x * MTILE;
    const int b = q0 >> 16;                  // QPB = 65536
    const int qbase = q0 & (QPB - 1);
    const float* xb = g_xt + b * (Hn * Wn * Cn);

    // ---------------- Stage A: build inp[m][36] (stored transposed) ---------
#pragma unroll 1
    for (int i = 0; i < 8; ++i) {
        int m = wid * 8 + i;
        int ql = qbase + m;
        int oy = ql >> 8, ox = ql & 255;
        float gy = (2.0f * oy + 1.0f) * (1.0f / 256.0f) - 1.0f;
        float gx = (2.0f * ox + 1.0f) * (1.0f / 256.0f) - 1.0f;
        int ix0, iy0;
        float wx[4], wy[4];
        prep_axis(gx, ix0, wx);
        prep_axis(gy, iy0, wy);
        float qf = sample_c(xb, lane, ix0, iy0, wx, wy);
        inpT[lane * STR + m] = qf;
        if (lane == 0) {
            float syw = 0.0f, sy = 0.0f, sxw = 0.0f, sx = 0.0f;
#pragma unroll
            for (int ii = 0; ii < 4; ++ii) {
                int yi = iy0 - 1 + ii;
                if ((unsigned)yi < 128u) {
                    float yco = (2.0f * yi + 1.0f) * (1.0f / 128.0f) - 1.0f;
                    syw += wy[ii];
                    sy = fmaf(wy[ii], yco, sy);
                }
            }
#pragma unroll
            for (int jj = 0; jj < 4; ++jj) {
                int xj = ix0 - 1 + jj;
                if ((unsigned)xj < 128u) {
                    float xco = (2.0f * xj + 1.0f) * (1.0f / 128.0f) - 1.0f;
                    sxw += wx[jj];
                    sx = fmaf(wx[jj], xco, sx);
                }
            }
            float qcy = sy * sxw;
            float qcx = sx * syw;
            inpT[32 * STR + m] = (gy - qcy) * 128.0f;
            inpT[33 * STR + m] = (gx - qcx) * 128.0f;
            float rc = (ql < 2) ? 1.0f : 128.0f;  // faithful cell quirk
            inpT[34 * STR + m] = rc;
            inpT[35 * STR + m] = rc;
        }
    }
    __syncthreads();

    // ---------------- MLP chain (bufA reused in place) ----------------------
    gemm_tile<36, 256, true>(inpT, w0, b0, bufA);
    __syncthreads();
    gemm_tile<256, 256, true>(bufA, w1, b1, bufA);     // in-place
    __syncthreads();
    gemm_tile<256, 32, false>(bufA, w2, b2, predT);
    __syncthreads();
    gemm_tile<32, 256, true>(predT, rw0, rb0, bufA);
    __syncthreads();
    gemm_tile<256, 32, false>(bufA, rw1, rb1, routT);
    __syncthreads();
    gemm_tile<32, 256, true>(predT, ow0, ob0, bufA);
    __syncthreads();

    // offset head: N=2 (m = tid/2, component = tid&1)
    if (tid < 128) {
        int m = tid >> 1, comp = tid & 1;
        const float* bb = bufA + m;
        float a0 = 0.f, a1 = 0.f, a2 = 0.f, a3 = 0.f;
#pragma unroll 4
        for (int k = 0; k < 256; k += 4) {
            a0 = fmaf(bb[(k + 0) * STR], __ldg(ow1 + (k + 0) * 2 + comp), a0);
            a1 = fmaf(bb[(k + 1) * STR], __ldg(ow1 + (k + 1) * 2 + comp), a1);
            a2 = fmaf(bb[(k + 2) * STR], __ldg(ow1 + (k + 2) * 2 + comp), a2);
            a3 = fmaf(bb[(k + 3) * STR], __ldg(ow1 + (k + 3) * 2 + comp), a3);
        }
        offs[m * 2 + comp] = (a0 + a1) + (a2 + a3) + __ldg(ob1 + comp);
    }
    __syncthreads();

    // ---------------- Stage C: offset resample + modulate -------------------
#pragma unroll 1
    for (int i = 0; i < 8; ++i) {
        int m = wid * 8 + i;
        int ql = qbase + m;
        int oy = ql >> 8, ox = ql & 255;
        float gy = (2.0f * oy + 1.0f) * (1.0f / 256.0f) - 1.0f;
        float gx = (2.0f * ox + 1.0f) * (1.0f / 256.0f) - 1.0f;
        float gx2 = gx + offs[m * 2 + 0];
        float gy2 = gy + offs[m * 2 + 1];
        int ix0, iy0;
        float wx[4], wy[4];
        prep_axis(gx2, ix0, wx);
        prep_axis(gy2, iy0, wy);
        float v = sample_c(xb, lane, ix0, iy0, wx, wy);
        float r = routT[lane * STR + m];
        inpT[lane * STR + m] = v * (1.0f + r);
    }
    __syncthreads();

    // coalesced writeout: out[(b*32+c)*65536 + qbase + m]
    {
        int c = tid >> 3;
        int part = tid & 7;
        const float* src = inpT + c * STR + part * 8;
        float* dst = out + ((size_t)(b * Cn + c)) * QPB + qbase + part * 8;
#pragma unroll
        for (int u = 0; u < 8; ++u) dst[u] = src[u];
    }
}

// ---------------------------------------------------------------------------
extern "C" void kernel_launch(void* const* d_in, const int* in_sizes, int n_in,
                              void* d_out, int out_size) {
    const float* x = (const float*)d_in[0];
    const float* w0 = (const float*)d_in[1];
    const float* b0 = (const float*)d_in[2];
    const float* w1 = (const float*)d_in[3];
    const float* b1 = (const float*)d_in[4];
    const float* w2 = (const float*)d_in[5];
    const float* b2 = (const float*)d_in[6];
    const float* rw0 = (const float*)d_in[7];
    const float* rb0 = (const float*)d_in[8];
    const float* rw1 = (const float*)d_in[9];
    const float* rb1 = (const float*)d_in[10];
    const float* ow0 = (const float*)d_in[11];
    const float* ob0 = (const float*)d_in[12];
    const float* ow1 = (const float*)d_in[13];
    const float* ob1 = (const float*)d_in[14];
    float* out = (float*)d_out;

    cudaFuncSetAttribute(fused_kernel,
                         cudaFuncAttributeMaxDynamicSharedMemorySize, SMEM_BYTES);

    xt_kernel<<<Bn * Hn, 256>>>(x);
    fused_kernel<<<NCTA, 256, SMEM_BYTES>>>(w0, b0, w1, b1, w2, b2,
                                            rw0, rb0, rw1, rb1,
                                            ow0, ob0, ow1, ob1, out);
}

// round 5
// speedup vs baseline: 1.7910x; 1.7910x over previous
#include <cuda_runtime.h>
#include <cuda_bf16.h>
#include <cstdint>

// ===========================================================================
// Problem constants (fixed: B=4, C=32, H=W=128, scale=2)
// ===========================================================================
#define Bn    4
#define Cn    32
#define Hn    128
#define Wn    128
#define QPB   65536
#define NQ    (Bn * QPB)
#define MT    128                  // queries per CTA
#define NCTA  (NQ / MT)            // 2048

// ===========================================================================
// Global scratch
// ===========================================================================
__device__ float g_xt[Bn * Hn * Wn * Cn];   // channels-last x

// Weight images: B-fragment-packed bf16, hi part then lo part (PSTR apart).
// Per layer: KC * NPT * 512 bytes  (KC = K/16 chunks, NPT = N/16 pairs)
#define WOFF_L1  0u          // KC=3,  NPT=16 -> 24576
#define WOFF_L2  24576u      // KC=16, NPT=16 -> 131072
#define WOFF_L3  155648u     // KC=16, NPT=2  -> 16384
#define WOFF_R0  172032u     // KC=2,  NPT=16 -> 16384
#define WOFF_R1  188416u     // KC=16, NPT=2  -> 16384
#define WOFF_O0  204800u     // KC=2,  NPT=16 -> 16384
#define WOFF_O1  221184u     // KC=16, NPT=1  -> 8192
#define PSTR     229376u
__device__ __align__(16) unsigned char g_wimg[2 * PSTR];

// ===========================================================================
// Transpose kernel: x[B,C,H,W] -> g_xt[B,H,W,C]
// ===========================================================================
__global__ void xt_kernel(const float* __restrict__ x) {
    __shared__ float s[Cn][Wn + 1];
    const int by = blockIdx.x;
    const int tid = threadIdx.x;
#pragma unroll
    for (int it = 0; it < 16; ++it) {
        int idx = tid + it * 256;
        int c = idx >> 7, xc = idx & 127;
        int b = by >> 7, y = by & 127;
        s[c][xc] = x[((b * Cn + c) * Hn + y) * Wn + xc];
    }
    __syncthreads();
#pragma unroll
    for (int it = 0; it < 16; ++it) {
        int idx = tid + it * 256;
        int xc = idx >> 5, c = idx & 31;
        g_xt[(by * Wn + xc) * Cn + c] = s[c][xc];
    }
}

// ===========================================================================
// Weight prep: W fp32 [Kdim][Ndim] -> B-fragment bf16 hi/lo images.
// Fragment (m16n8k16 B, col-major): lane = (n%8)*4 + (k%8)/2,
//   word = (k%16)/8 + ((n/8)%2)*2, half = k%2.
// 16B per lane per (kchunk, npair): [b0 even-nc, b1 even-nc, b0 odd, b1 odd]
// ===========================================================================
__global__ void prep_kernel(const float* __restrict__ W, int Kdim, int Ndim,
                            int Kt, int Nt, uint32_t dstOff) {
    int idx = blockIdx.x * 256 + threadIdx.x;
    if (idx >= Kt * Nt) return;
    int k = idx / Nt;
    int n = idx % Nt;
    float w = (k < Kdim && n < Ndim) ? W[k * Ndim + n] : 0.0f;
    __nv_bfloat16 hb = __float2bfloat16(w);
    float hf = __bfloat162float(hb);
    __nv_bfloat16 lb = __float2bfloat16(w - hf);
    int kc = k >> 4, ki = k & 15;
    int nc = n >> 3, ni = n & 7;
    int npair = nc >> 1;
    int lane = ni * 4 + ((ki & 7) >> 1);
    int word = (ki >> 3) + (nc & 1) * 2;
    int half = ki & 1;
    uint32_t off = (uint32_t)(((kc * (Nt >> 4) + npair) * 32 + lane) * 16 +
                              word * 4 + half * 2);
    *reinterpret_cast<unsigned short*>(g_wimg + dstOff + off) =
        *reinterpret_cast<unsigned short*>(&hb);
    *reinterpret_cast<unsigned short*>(g_wimg + dstOff + PSTR + off) =
        *reinterpret_cast<unsigned short*>(&lb);
}

// ===========================================================================
// Bicubic helpers (torch aten, A=-0.75)
// ===========================================================================
__device__ __forceinline__ void prep_axis(float g, int& i0, float w[4]) {
    float p = ((g + 1.0f) * 128.0f - 1.0f) * 0.5f;
    float fp = floorf(p);
    i0 = (int)fp;
    float t = p - fp;
    const float A = -0.75f;
    float xx = t + 1.0f;
    w[0] = ((A * xx - 5.0f * A) * xx + 8.0f * A) * xx - 4.0f * A;
    w[1] = ((A + 2.0f) * t - (A + 3.0f)) * t * t + 1.0f;
    float s = 1.0f - t;
    w[2] = ((A + 2.0f) * s - (A + 3.0f)) * s * s + 1.0f;
    w[3] = 1.0f - w[0] - w[1] - w[2];
}

__device__ __forceinline__ float sample_c(const float* __restrict__ xb, int lane,
                                          int ix0, int iy0,
                                          const float* wx, const float* wy) {
    float acc = 0.0f;
#pragma unroll
    for (int i = 0; i < 4; ++i) {
        int yi = iy0 - 1 + i;
        if ((unsigned)yi < 128u) {
            const float* rp = xb + yi * (Wn * Cn) + lane;
            float r = 0.0f;
#pragma unroll
            for (int j = 0; j < 4; ++j) {
                int xj = ix0 - 1 + j;
                if ((unsigned)xj < 128u) r = fmaf(wx[j], __ldg(rp + xj * Cn), r);
            }
            acc = fmaf(wy[i], r, acc);
        }
    }
    return acc;
}

// bf16 split + pack (v1 in high half, v0 in low half)
__device__ __forceinline__ void split_pack(float v0, float v1,
                                           uint32_t& hw, uint32_t& lw) {
    __nv_bfloat16 h0 = __float2bfloat16(v0);
    __nv_bfloat16 h1 = __float2bfloat16(v1);
    float f0 = __bfloat162float(h0), f1 = __bfloat162float(h1);
    __nv_bfloat16 l0 = __float2bfloat16(v0 - f0);
    __nv_bfloat16 l1 = __float2bfloat16(v1 - f1);
    unsigned short uh0 = *reinterpret_cast<unsigned short*>(&h0);
    unsigned short uh1 = *reinterpret_cast<unsigned short*>(&h1);
    unsigned short ul0 = *reinterpret_cast<unsigned short*>(&l0);
    unsigned short ul1 = *reinterpret_cast<unsigned short*>(&l1);
    hw = ((uint32_t)uh1 << 16) | uh0;
    lw = ((uint32_t)ul1 << 16) | ul0;
}

// ===========================================================================
// mma.sync m16n8k16 bf16 (legal on plain compute_103)
// ===========================================================================
__device__ __forceinline__ void mma_bf16(float* c, const uint4& a,
                                         uint32_t b0, uint32_t b1) {
    asm("mma.sync.aligned.m16n8k16.row.col.f32.bf16.bf16.f32 "
        "{%0,%1,%2,%3},{%4,%5,%6,%7},{%8,%9},{%0,%1,%2,%3};"
        : "+f"(c[0]), "+f"(c[1]), "+f"(c[2]), "+f"(c[3])
        : "r"(a.x), "r"(a.y), "r"(a.z), "r"(a.w), "r"(b0), "r"(b1));
}

// K-loop: C += Ah*Bh + Al*Bh + Ah*Bl over KC kchunks.
// A region layout: uint4 index = (kc*8 + rb)*32 + lane.
// B image layout:  uint4 index = (kc*NPT + npair)*32 + lane.
template <int KC, int NC, int NPT>
__device__ __forceinline__ void mma_layer(const uint4* __restrict__ aHi,
                                          const uint4* __restrict__ aLo,
                                          const uint4* __restrict__ bHi,
                                          const uint4* __restrict__ bLo,
                                          int rb0, int nc0, float C[2][NC][4]) {
    const int lane = threadIdx.x & 31;
#pragma unroll
    for (int r = 0; r < 2; ++r)
#pragma unroll
        for (int j = 0; j < NC; ++j)
#pragma unroll
            for (int t = 0; t < 4; ++t) C[r][j][t] = 0.0f;
    const int npair0 = nc0 >> 1;
#pragma unroll 1
    for (int kc = 0; kc < KC; ++kc) {
        uint4 ah0 = aHi[(kc * 8 + rb0) * 32 + lane];
        uint4 ah1 = aHi[(kc * 8 + rb0 + 1) * 32 + lane];
        uint4 al0 = aLo[(kc * 8 + rb0) * 32 + lane];
        uint4 al1 = aLo[(kc * 8 + rb0 + 1) * 32 + lane];
#pragma unroll
        for (int p = 0; p < NC / 2; ++p) {
            uint4 bh = __ldg(bHi + (kc * NPT + npair0 + p) * 32 + lane);
            uint4 bl = __ldg(bLo + (kc * NPT + npair0 + p) * 32 + lane);
            mma_bf16(C[0][2 * p], ah0, bh.x, bh.y);
            mma_bf16(C[1][2 * p], ah1, bh.x, bh.y);
            mma_bf16(C[0][2 * p + 1], ah0, bh.z, bh.w);
            mma_bf16(C[1][2 * p + 1], ah1, bh.z, bh.w);
            mma_bf16(C[0][2 * p], al0, bh.x, bh.y);
            mma_bf16(C[1][2 * p], al1, bh.x, bh.y);
            mma_bf16(C[0][2 * p + 1], al0, bh.z, bh.w);
            mma_bf16(C[1][2 * p + 1], al1, bh.z, bh.w);
            mma_bf16(C[0][2 * p], ah0, bl.x, bl.y);
            mma_bf16(C[1][2 * p], ah1, bl.x, bl.y);
            mma_bf16(C[0][2 * p + 1], ah0, bl.z, bl.w);
            mma_bf16(C[1][2 * p + 1], ah1, bl.z, bl.w);
        }
    }
}

// Epilogue: bias(+ReLU) then store as next layer's A fragments (hi/lo).
// C frag of output n-chunk nc maps to A kchunk nc/2, word pair (nc&1)*2.
template <int NC, bool RELU>
__device__ __forceinline__ void epi_region(float C[2][NC][4],
                                           const float* __restrict__ biasp,
                                           int rb0, int nc0,
                                           uint32_t* dHi, uint32_t* dLo) {
    const int lane = threadIdx.x & 31;
    const int q = (lane & 3) * 2;
#pragma unroll
    for (int j = 0; j < NC; ++j) {
        int nc = nc0 + j;
        int kc = nc >> 1, odd = nc & 1;
        float b0 = __ldg(biasp + nc * 8 + q);
        float b1 = __ldg(biasp + nc * 8 + q + 1);
#pragma unroll
        for (int r = 0; r < 2; ++r) {
            float v0 = C[r][j][0] + b0, v1 = C[r][j][1] + b1;
            float v2 = C[r][j][2] + b0, v3 = C[r][j][3] + b1;
            if (RELU) {
                v0 = fmaxf(v0, 0.f); v1 = fmaxf(v1, 0.f);
                v2 = fmaxf(v2, 0.f); v3 = fmaxf(v3, 0.f);
            }
            uint32_t h01, l01, h23, l23;
            split_pack(v0, v1, h01, l01);
            split_pack(v2, v3, h23, l23);
            int base = ((kc * 8 + rb0 + r) * 32 + lane) * 4 + odd * 2;
            dHi[base] = h01; dHi[base + 1] = h23;
            dLo[base] = l01; dLo[base + 1] = l23;
        }
    }
}

// ===========================================================================
// SMEM layout (bytes)
// ===========================================================================
#define SM_INPF  0          // fp32 [128][49] = 25088   (reused as routs [128][33])
#define SM_SHI   25088      // inp frags hi: 3*8*512 = 12288
#define SM_SLO   37376
#define SM_PHI   49664      // pred frags hi: 2*8*512 = 8192
#define SM_PLO   57856
#define SM_AHI   66048      // act frags hi: 16*8*512 = 65536
#define SM_ALO   131584
#define SM_OFFS  197120     // fp32 [128][2] = 1024
#define SM_OUT   198144     // fp32 [32][129] = 16512
#define SMEM_BYTES 214656

// ===========================================================================
// Fused kernel: 128 queries per CTA, 8 warps.
// Warp tile: rb0 = (wid&3)*2 (2 row-blocks = 32 rows), nhalf = wid>>2.
// ===========================================================================
__global__ __launch_bounds__(256, 1) void fused_kernel(
    const float* __restrict__ b0p, const float* __restrict__ b1p,
    const float* __restrict__ b2p, const float* __restrict__ rb0p,
    const float* __restrict__ rb1p, const float* __restrict__ ob0p,
    const float* __restrict__ ob1p, float* __restrict__ out) {
    extern __shared__ __align__(16) unsigned char smraw[];
    float* inpF = reinterpret_cast<float*>(smraw + SM_INPF);
    uint4* SHi = reinterpret_cast<uint4*>(smraw + SM_SHI);
    uint4* SLo = reinterpret_cast<uint4*>(smraw + SM_SLO);
    uint4* PHi = reinterpret_cast<uint4*>(smraw + SM_PHI);
    uint4* PLo = reinterpret_cast<uint4*>(smraw + SM_PLO);
    uint4* AHi = reinterpret_cast<uint4*>(smraw + SM_AHI);
    uint4* ALo = reinterpret_cast<uint4*>(smraw + SM_ALO);
    uint32_t* PHiW = reinterpret_cast<uint32_t*>(PHi);
    uint32_t* PLoW = reinterpret_cast<uint32_t*>(PLo);
    uint32_t* AHiW = reinterpret_cast<uint32_t*>(AHi);
    uint32_t* ALoW = reinterpret_cast<uint32_t*>(ALo);
    float* offs  = reinterpret_cast<float*>(smraw + SM_OFFS);
    float* outst = reinterpret_cast<float*>(smraw + SM_OUT);
    float* routs = inpF;   // reuse after L1 staging

    const int tid = threadIdx.x;
    const int lane = tid & 31;
    const int wid = tid >> 5;
    const int rb0 = (wid & 3) * 2;
    const int nhalf = wid >> 2;

    const int q0 = blockIdx.x * MT;
    const int b = q0 >> 16;
    const int qbase = q0 & (QPB - 1);
    const float* xb = g_xt + b * (Hn * Wn * Cn);

    const uint4* WL1H = (const uint4*)(g_wimg + WOFF_L1);
    const uint4* WL1L = (const uint4*)(g_wimg + WOFF_L1 + PSTR);
    const uint4* WL2H = (const uint4*)(g_wimg + WOFF_L2);
    const uint4* WL2L = (const uint4*)(g_wimg + WOFF_L2 + PSTR);
    const uint4* WL3H = (const uint4*)(g_wimg + WOFF_L3);
    const uint4* WL3L = (const uint4*)(g_wimg + WOFF_L3 + PSTR);
    const uint4* WR0H = (const uint4*)(g_wimg + WOFF_R0);
    const uint4* WR0L = (const uint4*)(g_wimg + WOFF_R0 + PSTR);
    const uint4* WR1H = (const uint4*)(g_wimg + WOFF_R1);
    const uint4* WR1L = (const uint4*)(g_wimg + WOFF_R1 + PSTR);
    const uint4* WO0H = (const uint4*)(g_wimg + WOFF_O0);
    const uint4* WO0L = (const uint4*)(g_wimg + WOFF_O0 + PSTR);
    const uint4* WO1H = (const uint4*)(g_wimg + WOFF_O1);
    const uint4* WO1L = (const uint4*)(g_wimg + WOFF_O1 + PSTR);

    // ---- Stage A: sampling -> inpF [128][49] -------------------------------
#pragma unroll 1
    for (int i = 0; i < 16; ++i) {
        int m = wid * 16 + i;
        int ql = qbase + m;
        int oy = ql >> 8, ox = ql & 255;
        float gy = (2.0f * oy + 1.0f) * (1.0f / 256.0f) - 1.0f;
        float gx = (2.0f * ox + 1.0f) * (1.0f / 256.0f) - 1.0f;
        int ix0, iy0;
        float wx[4], wy[4];
        prep_axis(gx, ix0, wx);
        prep_axis(gy, iy0, wy);
        inpF[m * 49 + lane] = sample_c(xb, lane, ix0, iy0, wx, wy);
        if (lane == 0) {
            float syw = 0.f, sy = 0.f, sxw = 0.f, sx = 0.f;
#pragma unroll
            for (int ii = 0; ii < 4; ++ii) {
                int yi = iy0 - 1 + ii;
                if ((unsigned)yi < 128u) {
                    float yco = (2.0f * yi + 1.0f) * (1.0f / 128.0f) - 1.0f;
                    syw += wy[ii]; sy = fmaf(wy[ii], yco, sy);
                }
            }
#pragma unroll
            for (int jj = 0; jj < 4; ++jj) {
                int xj = ix0 - 1 + jj;
                if ((unsigned)xj < 128u) {
                    float xco = (2.0f * xj + 1.0f) * (1.0f / 128.0f) - 1.0f;
                    sxw += wx[jj]; sx = fmaf(wx[jj], xco, sx);
                }
            }
            inpF[m * 49 + 32] = (gy - sy * sxw) * 128.0f;
            inpF[m * 49 + 33] = (gx - sx * syw) * 128.0f;
            float rc = (ql < 2) ? 1.0f : 128.0f;   // faithful cell quirk
            inpF[m * 49 + 34] = rc;
            inpF[m * 49 + 35] = rc;
        }
        if (lane >= 4 && lane < 16) inpF[m * 49 + 32 + lane] = 0.0f;  // pad 36..47
    }
    __syncthreads();

    // ---- Stage S frags: inpF -> S (A-fragment bf16 hi/lo, K=48) -------------
#pragma unroll
    for (int i = 0; i < 3; ++i) {
        int kc = i, rb = wid;
        int r0 = rb * 16 + (lane >> 2);
        int k0 = kc * 16 + (lane & 3) * 2;
        float v00 = inpF[r0 * 49 + k0],       v01 = inpF[r0 * 49 + k0 + 1];
        float v10 = inpF[(r0 + 8) * 49 + k0], v11 = inpF[(r0 + 8) * 49 + k0 + 1];
        float v02 = inpF[r0 * 49 + k0 + 8],   v03 = inpF[r0 * 49 + k0 + 9];
        float v12 = inpF[(r0 + 8) * 49 + k0 + 8], v13 = inpF[(r0 + 8) * 49 + k0 + 9];
        uint4 hi, lo;
        split_pack(v00, v01, hi.x, lo.x);
        split_pack(v10, v11, hi.y, lo.y);
        split_pack(v02, v03, hi.z, lo.z);
        split_pack(v12, v13, hi.w, lo.w);
        SHi[(kc * 8 + rb) * 32 + lane] = hi;
        SLo[(kc * 8 + rb) * 32 + lane] = lo;
    }
    __syncthreads();

    float C16[2][16][4];
    float C2[2][2][4];

    // ---- L1: S(K=48) x W0 -> h1 (N=256) -> A --------------------------------
    mma_layer<3, 16, 16>(SHi, SLo, WL1H, WL1L, rb0, nhalf * 16, C16);
    epi_region<16, true>(C16, b0p, rb0, nhalf * 16, AHiW, ALoW);
    __syncthreads();

    // ---- L2: A(K=256) x W1 -> h2 (N=256) -> A (in place) --------------------
    mma_layer<16, 16, 16>(AHi, ALo, WL2H, WL2L, rb0, nhalf * 16, C16);
    __syncthreads();   // all reads of A done before overwriting
    epi_region<16, true>(C16, b1p, rb0, nhalf * 16, AHiW, ALoW);
    __syncthreads();

    // ---- L3: A(K=256) x W2 -> pred (N=32, no relu) -> P ----------------------
    mma_layer<16, 2, 2>(AHi, ALo, WL3H, WL3L, rb0, nhalf * 2, C2);
    epi_region<2, false>(C2, b2p, rb0, nhalf * 2, PHiW, PLoW);
    __syncthreads();

    // ---- O0: P(K=32) x OW0 -> off-hidden (N=256) -> A ------------------------
    mma_layer<2, 16, 16>(PHi, PLo, WO0H, WO0L, rb0, nhalf * 16, C16);
    epi_region<16, true>(C16, ob0p, rb0, nhalf * 16, AHiW, ALoW);
    __syncthreads();

    // ---- O1: A(K=256) x OW1 -> offsets (cols 0,1) ----------------------------
    if (wid < 4) {
        mma_layer<16, 2, 1>(AHi, ALo, WO1H, WO1L, rb0, 0, C2);
        if ((lane & 3) == 0) {
            float o0 = __ldg(ob1p + 0), o1 = __ldg(ob1p + 1);
#pragma unroll
            for (int r = 0; r < 2; ++r) {
                int row = (rb0 + r) * 16 + (lane >> 2);
                offs[row * 2 + 0] = C2[r][0][0] + o0;
                offs[row * 2 + 1] = C2[r][0][1] + o1;
                offs[(row + 8) * 2 + 0] = C2[r][0][2] + o0;
                offs[(row + 8) * 2 + 1] = C2[r][0][3] + o1;
            }
        }
    }
    __syncthreads();

    // ---- R0: P(K=32) x RW0 -> rout-hidden (N=256) -> A ------------------------
    mma_layer<2, 16, 16>(PHi, PLo, WR0H, WR0L, rb0, nhalf * 16, C16);
    epi_region<16, true>(C16, rb0p, rb0, nhalf * 16, AHiW, ALoW);
    __syncthreads();

    // ---- R1: A(K=256) x RW1 -> routing (N=32) -> routs fp32 -------------------
    mma_layer<16, 2, 2>(AHi, ALo, WR1H, WR1L, rb0, nhalf * 2, C2);
    {
        const int q = (lane & 3) * 2;
#pragma unroll
        for (int j = 0; j < 2; ++j) {
            int nc = nhalf * 2 + j;
            float bb0 = __ldg(rb1p + nc * 8 + q);
            float bb1 = __ldg(rb1p + nc * 8 + q + 1);
#pragma unroll
            for (int r = 0; r < 2; ++r) {
                int row = (rb0 + r) * 16 + (lane >> 2);
                routs[row * 33 + nc * 8 + q]     = C2[r][j][0] + bb0;
                routs[row * 33 + nc * 8 + q + 1] = C2[r][j][1] + bb1;
                routs[(row + 8) * 33 + nc * 8 + q]     = C2[r][j][2] + bb0;
                routs[(row + 8) * 33 + nc * 8 + q + 1] = C2[r][j][3] + bb1;
            }
        }
    }
    __syncthreads();

    // ---- Stage C: offset resample + modulate ---------------------------------
#pragma unroll 1
    for (int i = 0; i < 16; ++i) {
        int m = wid * 16 + i;
        int ql = qbase + m;
        int oy = ql >> 8, ox = ql & 255;
        float gy = (2.0f * oy + 1.0f) * (1.0f / 256.0f) - 1.0f;
        float gx = (2.0f * ox + 1.0f) * (1.0f / 256.0f) - 1.0f;
        float gx2 = gx + offs[m * 2 + 0];
        float gy2 = gy + offs[m * 2 + 1];
        int ix0, iy0;
        float wx[4], wy[4];
        prep_axis(gx2, ix0, wx);
        prep_axis(gy2, iy0, wy);
        float v = sample_c(xb, lane, ix0, iy0, wx, wy);
        outst[lane * 129 + m] = v * (1.0f + routs[m * 33 + lane]);
    }
    __syncthreads();

    // ---- writeout -------------------------------------------------------------
    {
        int c = tid >> 3;
        int part = tid & 7;
        const float* src = outst + c * 129 + part * 16;
        float* dst = out + ((size_t)(b * Cn + c)) * QPB + qbase + part * 16;
#pragma unroll
        for (int u = 0; u < 4; ++u)
            *reinterpret_cast<float4*>(dst + 4 * u) =
                make_float4(src[4 * u], src[4 * u + 1], src[4 * u + 2], src[4 * u + 3]);
    }
}

// ===========================================================================
// kernel_launch
// ===========================================================================
extern "C" void kernel_launch(void* const* d_in, const int* in_sizes, int n_in,
                              void* d_out, int out_size) {
    const float* x   = (const float*)d_in[0];
    const float* w0  = (const float*)d_in[1];
    const float* b0  = (const float*)d_in[2];
    const float* w1  = (const float*)d_in[3];
    const float* b1  = (const float*)d_in[4];
    const float* w2  = (const float*)d_in[5];
    const float* b2  = (const float*)d_in[6];
    const float* rw0 = (const float*)d_in[7];
    const float* rb0 = (const float*)d_in[8];
    const float* rw1 = (const float*)d_in[9];
    const float* rb1 = (const float*)d_in[10];
    const float* ow0 = (const float*)d_in[11];
    const float* ob0 = (const float*)d_in[12];
    const float* ow1 = (const float*)d_in[13];
    const float* ob1 = (const float*)d_in[14];
    float* out = (float*)d_out;

    xt_kernel<<<Bn * Hn, 256>>>(x);

    auto prep = [&](const float* W, int K, int N, int Kt, int Nt, uint32_t off) {
        prep_kernel<<<(Kt * Nt + 255) / 256, 256>>>(W, K, N, Kt, Nt, off);
    };
    prep(w0,  36, 256, 48, 256, WOFF_L1);
    prep(w1, 256, 256, 256, 256, WOFF_L2);
    prep(w2, 256, 32, 256, 32, WOFF_L3);
    prep(rw0, 32, 256, 32, 256, WOFF_R0);
    prep(rw1, 256, 32, 256, 32, WOFF_R1);
    prep(ow0, 32, 256, 32, 256, WOFF_O0);
    prep(ow1, 256, 2, 256, 16, WOFF_O1);

    cudaFuncSetAttribute(fused_kernel,
                         cudaFuncAttributeMaxDynamicSharedMemorySize, SMEM_BYTES);
    fused_kernel<<<NCTA, 256, SMEM_BYTES>>>(b0, b1, b2, rb0, rb1, ob0, ob1, out);
}

// round 6
// speedup vs baseline: 2.2306x; 1.2454x over previous
#include <cuda_runtime.h>
#include <cuda_bf16.h>
#include <cstdint>

// ===========================================================================
// Problem constants (fixed: B=4, C=32, H=W=128, scale=2)
// ===========================================================================
#define Bn    4
#define Cn    32
#define Hn    128
#define Wn    128
#define QPB   65536
#define NQ    (Bn * QPB)
#define MT    64                   // queries per CTA
#define NCTA  (NQ / MT)            // 4096
#define NRB   4                    // row-blocks (16 rows) per CTA

// ===========================================================================
// Global scratch
// ===========================================================================
__device__ float g_xt[Bn * Hn * Wn * Cn];   // channels-last x

// Weight images: B-fragment-packed bf16, hi part then lo part (PSTR apart).
// Per layer: KC * NPT * 512 bytes  (KC = K/16 chunks, NPT = N/16 pairs)
#define WOFF_L1  0u          // KC=3,  NPT=16 -> 24576
#define WOFF_L2  24576u      // KC=16, NPT=16 -> 131072
#define WOFF_L3  155648u     // KC=16, NPT=2  -> 16384
#define WOFF_R0  172032u     // KC=2,  NPT=16 -> 16384
#define WOFF_R1  188416u     // KC=16, NPT=2  -> 16384
#define WOFF_O0  204800u     // KC=2,  NPT=16 -> 16384
#define WOFF_O1  221184u     // KC=16, NPT=1  -> 8192
#define PSTR     229376u
__device__ __align__(16) unsigned char g_wimg[2 * PSTR];

// ===========================================================================
// Transpose kernel: x[B,C,H,W] -> g_xt[B,H,W,C]
// ===========================================================================
__global__ void xt_kernel(const float* __restrict__ x) {
    __shared__ float s[Cn][Wn + 1];
    const int by = blockIdx.x;
    const int tid = threadIdx.x;
#pragma unroll
    for (int it = 0; it < 16; ++it) {
        int idx = tid + it * 256;
        int c = idx >> 7, xc = idx & 127;
        int b = by >> 7, y = by & 127;
        s[c][xc] = x[((b * Cn + c) * Hn + y) * Wn + xc];
    }
    __syncthreads();
#pragma unroll
    for (int it = 0; it < 16; ++it) {
        int idx = tid + it * 256;
        int xc = idx >> 5, c = idx & 31;
        g_xt[(by * Wn + xc) * Cn + c] = s[c][xc];
    }
}

// ===========================================================================
// Weight prep: W fp32 [Kdim][Ndim] -> B-fragment bf16 hi/lo images.
// ===========================================================================
__global__ void prep_kernel(const float* __restrict__ W, int Kdim, int Ndim,
                            int Kt, int Nt, uint32_t dstOff) {
    int idx = blockIdx.x * 256 + threadIdx.x;
    if (idx >= Kt * Nt) return;
    int k = idx / Nt;
    int n = idx % Nt;
    float w = (k < Kdim && n < Ndim) ? W[k * Ndim + n] : 0.0f;
    __nv_bfloat16 hb = __float2bfloat16(w);
    float hf = __bfloat162float(hb);
    __nv_bfloat16 lb = __float2bfloat16(w - hf);
    int kc = k >> 4, ki = k & 15;
    int nc = n >> 3, ni = n & 7;
    int npair = nc >> 1;
    int lane = ni * 4 + ((ki & 7) >> 1);
    int word = (ki >> 3) + (nc & 1) * 2;
    int half = ki & 1;
    uint32_t off = (uint32_t)(((kc * (Nt >> 4) + npair) * 32 + lane) * 16 +
                              word * 4 + half * 2);
    *reinterpret_cast<unsigned short*>(g_wimg + dstOff + off) =
        *reinterpret_cast<unsigned short*>(&hb);
    *reinterpret_cast<unsigned short*>(g_wimg + dstOff + PSTR + off) =
        *reinterpret_cast<unsigned short*>(&lb);
}

// ===========================================================================
// Bicubic helpers (torch aten, A=-0.75)
// ===========================================================================
__device__ __forceinline__ void prep_axis(float g, int& i0, float w[4]) {
    float p = ((g + 1.0f) * 128.0f - 1.0f) * 0.5f;
    float fp = floorf(p);
    i0 = (int)fp;
    float t = p - fp;
    const float A = -0.75f;
    float xx = t + 1.0f;
    w[0] = ((A * xx - 5.0f * A) * xx + 8.0f * A) * xx - 4.0f * A;
    w[1] = ((A + 2.0f) * t - (A + 3.0f)) * t * t + 1.0f;
    float s = 1.0f - t;
    w[2] = ((A + 2.0f) * s - (A + 3.0f)) * s * s + 1.0f;
    w[3] = 1.0f - w[0] - w[1] - w[2];
}

__device__ __forceinline__ float sample_c(const float* __restrict__ xb, int lane,
                                          int ix0, int iy0,
                                          const float* wx, const float* wy) {
    float acc = 0.0f;
#pragma unroll
    for (int i = 0; i < 4; ++i) {
        int yi = iy0 - 1 + i;
        if ((unsigned)yi < 128u) {
            const float* rp = xb + yi * (Wn * Cn) + lane;
            float r = 0.0f;
#pragma unroll
            for (int j = 0; j < 4; ++j) {
                int xj = ix0 - 1 + j;
                if ((unsigned)xj < 128u) r = fmaf(wx[j], __ldg(rp + xj * Cn), r);
            }
            acc = fmaf(wy[i], r, acc);
        }
    }
    return acc;
}

// bf16 split + pack (v1 in high half, v0 in low half)
__device__ __forceinline__ void split_pack(float v0, float v1,
                                           uint32_t& hw, uint32_t& lw) {
    __nv_bfloat16 h0 = __float2bfloat16(v0);
    __nv_bfloat16 h1 = __float2bfloat16(v1);
    float f0 = __bfloat162float(h0), f1 = __bfloat162float(h1);
    __nv_bfloat16 l0 = __float2bfloat16(v0 - f0);
    __nv_bfloat16 l1 = __float2bfloat16(v1 - f1);
    unsigned short uh0 = *reinterpret_cast<unsigned short*>(&h0);
    unsigned short uh1 = *reinterpret_cast<unsigned short*>(&h1);
    unsigned short ul0 = *reinterpret_cast<unsigned short*>(&l0);
    unsigned short ul1 = *reinterpret_cast<unsigned short*>(&l1);
    hw = ((uint32_t)uh1 << 16) | uh0;
    lw = ((uint32_t)ul1 << 16) | ul0;
}

// ===========================================================================
// mma.sync m16n8k16 bf16
// ===========================================================================
__device__ __forceinline__ void mma_bf16(float* c, const uint4& a,
                                         uint32_t b0, uint32_t b1) {
    asm("mma.sync.aligned.m16n8k16.row.col.f32.bf16.bf16.f32 "
        "{%0,%1,%2,%3},{%4,%5,%6,%7},{%8,%9},{%0,%1,%2,%3};"
        : "+f"(c[0]), "+f"(c[1]), "+f"(c[2]), "+f"(c[3])
        : "r"(a.x), "r"(a.y), "r"(a.z), "r"(a.w), "r"(b0), "r"(b1));
}

// K-loop over one 16-row block: C += Ah*Bh + Al*Bh + Ah*Bl.
// A region layout: uint4 index = (kc*NRB + rb)*32 + lane.
// B image layout:  uint4 index = (kc*NPT + npair)*32 + lane.
template <int KC, int NC, int NPT>
__device__ __forceinline__ void mma_layer(const uint4* __restrict__ aHi,
                                          const uint4* __restrict__ aLo,
                                          const uint4* __restrict__ bHi,
                                          const uint4* __restrict__ bLo,
                                          int rb, int nc0, float C[NC][4]) {
    const int lane = threadIdx.x & 31;
#pragma unroll
    for (int j = 0; j < NC; ++j)
#pragma unroll
        for (int t = 0; t < 4; ++t) C[j][t] = 0.0f;
    const int npair0 = nc0 >> 1;
#pragma unroll 1
    for (int kc = 0; kc < KC; ++kc) {
        uint4 ah = aHi[(kc * NRB + rb) * 32 + lane];
        uint4 al = aLo[(kc * NRB + rb) * 32 + lane];
#pragma unroll
        for (int p = 0; p < NC / 2; ++p) {
            uint4 bh = __ldg(bHi + (kc * NPT + npair0 + p) * 32 + lane);
            uint4 bl = __ldg(bLo + (kc * NPT + npair0 + p) * 32 + lane);
            mma_bf16(C[2 * p], ah, bh.x, bh.y);
            mma_bf16(C[2 * p + 1], ah, bh.z, bh.w);
            mma_bf16(C[2 * p], al, bh.x, bh.y);
            mma_bf16(C[2 * p + 1], al, bh.z, bh.w);
            mma_bf16(C[2 * p], ah, bl.x, bl.y);
            mma_bf16(C[2 * p + 1], ah, bl.z, bl.w);
        }
    }
}

// Epilogue: bias(+ReLU), split to bf16 hi/lo A fragments for the next layer.
// Output n-chunk nc -> A kchunk nc/2, word pair (nc&1)*2.
template <int NC, bool RELU>
__device__ __forceinline__ void epi_region(float C[NC][4],
                                           const float* __restrict__ biasp,
                                           int rb, int nc0,
                                           uint32_t* dHi, uint32_t* dLo) {
    const int lane = threadIdx.x & 31;
    const int q = (lane & 3) * 2;
#pragma unroll
    for (int j = 0; j < NC; ++j) {
        int nc = nc0 + j;
        int kc = nc >> 1, odd = nc & 1;
        float b0 = __ldg(biasp + nc * 8 + q);
        float b1 = __ldg(biasp + nc * 8 + q + 1);
        float v0 = C[j][0] + b0, v1 = C[j][1] + b1;
        float v2 = C[j][2] + b0, v3 = C[j][3] + b1;
        if (RELU) {
            v0 = fmaxf(v0, 0.f); v1 = fmaxf(v1, 0.f);
            v2 = fmaxf(v2, 0.f); v3 = fmaxf(v3, 0.f);
        }
        uint32_t h01, l01, h23, l23;
        split_pack(v0, v1, h01, l01);
        split_pack(v2, v3, h23, l23);
        int base = ((kc * NRB + rb) * 32 + lane) * 4 + odd * 2;
        dHi[base] = h01; dHi[base + 1] = h23;
        dLo[base] = l01; dLo[base + 1] = l23;
    }
}

// ===========================================================================
// SMEM layout (bytes) — total 107392 -> 2 CTAs/SM
// ===========================================================================
#define SM_INPF  0          // fp32 [64][49] = 12544 (reused as routs [64][33])
#define SM_SHI   12544      // inp frags hi: 3*4*512 = 6144
#define SM_SLO   18688
#define SM_PHI   24832      // pred frags hi: 2*4*512 = 4096
#define SM_PLO   28928
#define SM_AHI   33024      // act frags hi: 16*4*512 = 32768
#define SM_ALO   65792
#define SM_OFFS  98560      // fp32 [64][2] = 512
#define SM_OUT   99072      // fp32 [32][65] = 8320
#define SMEM_BYTES 107392

// ===========================================================================
// Fused kernel: 64 queries per CTA, 8 warps, 2 CTAs/SM.
// Warp tile: rb = wid&3 (16 rows), nhalf = wid>>2 (128 of 256 N cols).
// ===========================================================================
__global__ __launch_bounds__(256, 2) void fused_kernel(
    const float* __restrict__ b0p, const float* __restrict__ b1p,
    const float* __restrict__ b2p, const float* __restrict__ rb0p,
    const float* __restrict__ rb1p, const float* __restrict__ ob0p,
    const float* __restrict__ ob1p, float* __restrict__ out) {
    extern __shared__ __align__(16) unsigned char smraw[];
    float* inpF = reinterpret_cast<float*>(smraw + SM_INPF);
    uint4* SHi = reinterpret_cast<uint4*>(smraw + SM_SHI);
    uint4* SLo = reinterpret_cast<uint4*>(smraw + SM_SLO);
    uint4* PHi = reinterpret_cast<uint4*>(smraw + SM_PHI);
    uint4* PLo = reinterpret_cast<uint4*>(smraw + SM_PLO);
    uint4* AHi = reinterpret_cast<uint4*>(smraw + SM_AHI);
    uint4* ALo = reinterpret_cast<uint4*>(smraw + SM_ALO);
    uint32_t* PHiW = reinterpret_cast<uint32_t*>(PHi);
    uint32_t* PLoW = reinterpret_cast<uint32_t*>(PLo);
    uint32_t* AHiW = reinterpret_cast<uint32_t*>(AHi);
    uint32_t* ALoW = reinterpret_cast<uint32_t*>(ALo);
    float* offs  = reinterpret_cast<float*>(smraw + SM_OFFS);
    float* outst = reinterpret_cast<float*>(smraw + SM_OUT);
    float* routs = inpF;   // reuse after L1 staging

    const int tid = threadIdx.x;
    const int lane = tid & 31;
    const int wid = tid >> 5;
    const int rb = wid & 3;
    const int nhalf = wid >> 2;

    const int q0 = blockIdx.x * MT;
    const int b = q0 >> 16;
    const int qbase = q0 & (QPB - 1);
    const float* xb = g_xt + b * (Hn * Wn * Cn);

    const uint4* WL1H = (const uint4*)(g_wimg + WOFF_L1);
    const uint4* WL1L = (const uint4*)(g_wimg + WOFF_L1 + PSTR);
    const uint4* WL2H = (const uint4*)(g_wimg + WOFF_L2);
    const uint4* WL2L = (const uint4*)(g_wimg + WOFF_L2 + PSTR);
    const uint4* WL3H = (const uint4*)(g_wimg + WOFF_L3);
    const uint4* WL3L = (const uint4*)(g_wimg + WOFF_L3 + PSTR);
    const uint4* WR0H = (const uint4*)(g_wimg + WOFF_R0);
    const uint4* WR0L = (const uint4*)(g_wimg + WOFF_R0 + PSTR);
    const uint4* WR1H = (const uint4*)(g_wimg + WOFF_R1);
    const uint4* WR1L = (const uint4*)(g_wimg + WOFF_R1 + PSTR);
    const uint4* WO0H = (const uint4*)(g_wimg + WOFF_O0);
    const uint4* WO0L = (const uint4*)(g_wimg + WOFF_O0 + PSTR);
    const uint4* WO1H = (const uint4*)(g_wimg + WOFF_O1);
    const uint4* WO1L = (const uint4*)(g_wimg + WOFF_O1 + PSTR);

    // ---- Stage A: sampling -> inpF [64][49] --------------------------------
#pragma unroll 1
    for (int i = 0; i < 8; ++i) {
        int m = wid * 8 + i;
        int ql = qbase + m;
        int oy = ql >> 8, ox = ql & 255;
        float gy = (2.0f * oy + 1.0f) * (1.0f / 256.0f) - 1.0f;
        float gx = (2.0f * ox + 1.0f) * (1.0f / 256.0f) - 1.0f;
        int ix0, iy0;
        float wx[4], wy[4];
        prep_axis(gx, ix0, wx);
        prep_axis(gy, iy0, wy);
        inpF[m * 49 + lane] = sample_c(xb, lane, ix0, iy0, wx, wy);
        if (lane == 0) {
            float syw = 0.f, sy = 0.f, sxw = 0.f, sx = 0.f;
#pragma unroll
            for (int ii = 0; ii < 4; ++ii) {
                int yi = iy0 - 1 + ii;
                if ((unsigned)yi < 128u) {
                    float yco = (2.0f * yi + 1.0f) * (1.0f / 128.0f) - 1.0f;
                    syw += wy[ii]; sy = fmaf(wy[ii], yco, sy);
                }
            }
#pragma unroll
            for (int jj = 0; jj < 4; ++jj) {
                int xj = ix0 - 1 + jj;
                if ((unsigned)xj < 128u) {
                    float xco = (2.0f * xj + 1.0f) * (1.0f / 128.0f) - 1.0f;
                    sxw += wx[jj]; sx = fmaf(wx[jj], xco, sx);
                }
            }
            inpF[m * 49 + 32] = (gy - sy * sxw) * 128.0f;
            inpF[m * 49 + 33] = (gx - sx * syw) * 128.0f;
            float rc = (ql < 2) ? 1.0f : 128.0f;   // faithful cell quirk
            inpF[m * 49 + 34] = rc;
            inpF[m * 49 + 35] = rc;
        }
        if (lane >= 4 && lane < 16) inpF[m * 49 + 32 + lane] = 0.0f;  // pad 36..47
    }
    __syncthreads();

    // ---- Stage S frags: inpF -> S (A-fragment bf16 hi/lo, K=48) -------------
    // 12 (kc, rb) combos over 8 warps
#pragma unroll
    for (int i = 0; i < 2; ++i) {
        int idx = wid + i * 8;
        if (idx < 12) {
            int kc = idx >> 2, rbs = idx & 3;
            int r0 = rbs * 16 + (lane >> 2);
            int k0 = kc * 16 + (lane & 3) * 2;
            float v00 = inpF[r0 * 49 + k0],       v01 = inpF[r0 * 49 + k0 + 1];
            float v10 = inpF[(r0 + 8) * 49 + k0], v11 = inpF[(r0 + 8) * 49 + k0 + 1];
            float v02 = inpF[r0 * 49 + k0 + 8],   v03 = inpF[r0 * 49 + k0 + 9];
            float v12 = inpF[(r0 + 8) * 49 + k0 + 8], v13 = inpF[(r0 + 8) * 49 + k0 + 9];
            uint4 hi, lo;
            split_pack(v00, v01, hi.x, lo.x);
            split_pack(v10, v11, hi.y, lo.y);
            split_pack(v02, v03, hi.z, lo.z);
            split_pack(v12, v13, hi.w, lo.w);
            SHi[(kc * NRB + rbs) * 32 + lane] = hi;
            SLo[(kc * NRB + rbs) * 32 + lane] = lo;
        }
    }
    __syncthreads();

    float C16[16][4];
    float C2[2][4];

    // ---- L1: S(K=48) x W0 -> h1 (N=256) -> A --------------------------------
    mma_layer<3, 16, 16>(SHi, SLo, WL1H, WL1L, rb, nhalf * 16, C16);
    epi_region<16, true>(C16, b0p, rb, nhalf * 16, AHiW, ALoW);
    __syncthreads();

    // ---- L2: A(K=256) x W1 -> h2 (N=256) -> A (in place) --------------------
    mma_layer<16, 16, 16>(AHi, ALo, WL2H, WL2L, rb, nhalf * 16, C16);
    __syncthreads();   // all reads of A done before overwriting
    epi_region<16, true>(C16, b1p, rb, nhalf * 16, AHiW, ALoW);
    __syncthreads();

    // ---- L3: A(K=256) x W2 -> pred (N=32, no relu) -> P ----------------------
    mma_layer<16, 2, 2>(AHi, ALo, WL3H, WL3L, rb, nhalf * 2, C2);
    epi_region<2, false>(C2, b2p, rb, nhalf * 2, PHiW, PLoW);
    __syncthreads();

    // ---- O0: P(K=32) x OW0 -> off-hidden (N=256) -> A ------------------------
    mma_layer<2, 16, 16>(PHi, PLo, WO0H, WO0L, rb, nhalf * 16, C16);
    epi_region<16, true>(C16, ob0p, rb, nhalf * 16, AHiW, ALoW);
    __syncthreads();

    // ---- O1: A(K=256) x OW1 -> offsets (cols 0,1) ----------------------------
    if (nhalf == 0) {
        mma_layer<16, 2, 1>(AHi, ALo, WO1H, WO1L, rb, 0, C2);
        if ((lane & 3) == 0) {
            float o0 = __ldg(ob1p + 0), o1 = __ldg(ob1p + 1);
            int row = rb * 16 + (lane >> 2);
            offs[row * 2 + 0] = C2[0][0] + o0;
            offs[row * 2 + 1] = C2[0][1] + o1;
            offs[(row + 8) * 2 + 0] = C2[0][2] + o0;
            offs[(row + 8) * 2 + 1] = C2[0][3] + o1;
        }
    }
    __syncthreads();

    // ---- R0: P(K=32) x RW0 -> rout-hidden (N=256) -> A ------------------------
    mma_layer<2, 16, 16>(PHi, PLo, WR0H, WR0L, rb, nhalf * 16, C16);
    epi_region<16, true>(C16, rb0p, rb, nhalf * 16, AHiW, ALoW);
    __syncthreads();

    // ---- R1: A(K=256) x RW1 -> routing (N=32) -> routs fp32 -------------------
    mma_layer<16, 2, 2>(AHi, ALo, WR1H, WR1L, rb, nhalf * 2, C2);
    __syncthreads();   // A reads done; routs aliases inpF (distinct) but keep order
    {
        const int q = (lane & 3) * 2;
#pragma unroll
        for (int j = 0; j < 2; ++j) {
            int nc = nhalf * 2 + j;
            float bb0 = __ldg(rb1p + nc * 8 + q);
            float bb1 = __ldg(rb1p + nc * 8 + q + 1);
            int row = rb * 16 + (lane >> 2);
            routs[row * 33 + nc * 8 + q]     = C2[j][0] + bb0;
            routs[row * 33 + nc * 8 + q + 1] = C2[j][1] + bb1;
            routs[(row + 8) * 33 + nc * 8 + q]     = C2[j][2] + bb0;
            routs[(row + 8) * 33 + nc * 8 + q + 1] = C2[j][3] + bb1;
        }
    }
    __syncthreads();

    // ---- Stage C: offset resample + modulate ---------------------------------
#pragma unroll 1
    for (int i = 0; i < 8; ++i) {
        int m = wid * 8 + i;
        int ql = qbase + m;
        int oy = ql >> 8, ox = ql & 255;
        float gy = (2.0f * oy + 1.0f) * (1.0f / 256.0f) - 1.0f;
        float gx = (2.0f * ox + 1.0f) * (1.0f / 256.0f) - 1.0f;
        float gx2 = gx + offs[m * 2 + 0];
        float gy2 = gy + offs[m * 2 + 1];
        int ix0, iy0;
        float wx[4], wy[4];
        prep_axis(gx2, ix0, wx);
        prep_axis(gy2, iy0, wy);
        float v = sample_c(xb, lane, ix0, iy0, wx, wy);
        outst[lane * 65 + m] = v * (1.0f + routs[m * 33 + lane]);
    }
    __syncthreads();

    // ---- writeout -------------------------------------------------------------
    {
        int c = tid >> 3;
        int part = tid & 7;
        const float* src = outst + c * 65 + part * 8;
        float* dst = out + ((size_t)(b * Cn + c)) * QPB + qbase + part * 8;
        *reinterpret_cast<float4*>(dst) =
            make_float4(src[0], src[1], src[2], src[3]);
        *reinterpret_cast<float4*>(dst + 4) =
            make_float4(src[4], src[5], src[6], src[7]);
    }
}

// ===========================================================================
// kernel_launch
// ===========================================================================
extern "C" void kernel_launch(void* const* d_in, const int* in_sizes, int n_in,
                              void* d_out, int out_size) {
    const float* x   = (const float*)d_in[0];
    const float* w0  = (const float*)d_in[1];
    const float* b0  = (const float*)d_in[2];
    const float* w1  = (const float*)d_in[3];
    const float* b1  = (const float*)d_in[4];
    const float* w2  = (const float*)d_in[5];
    const float* b2  = (const float*)d_in[6];
    const float* rw0 = (const float*)d_in[7];
    const float* rb0 = (const float*)d_in[8];
    const float* rw1 = (const float*)d_in[9];
    const float* rb1 = (const float*)d_in[10];
    const float* ow0 = (const float*)d_in[11];
    const float* ob0 = (const float*)d_in[12];
    const float* ow1 = (const float*)d_in[13];
    const float* ob1 = (const float*)d_in[14];
    float* out = (float*)d_out;

    xt_kernel<<<Bn * Hn, 256>>>(x);

    auto prep = [&](const float* W, int K, int N, int Kt, int Nt, uint32_t off) {
        prep_kernel<<<(Kt * Nt + 255) / 256, 256>>>(W, K, N, Kt, Nt, off);
    };
    prep(w0,  36, 256, 48, 256, WOFF_L1);
    prep(w1, 256, 256, 256, 256, WOFF_L2);
    prep(w2, 256, 32, 256, 32, WOFF_L3);
    prep(rw0, 32, 256, 32, 256, WOFF_R0);
    prep(rw1, 256, 32, 256, 32, WOFF_R1);
    prep(ow0, 32, 256, 32, 256, WOFF_O0);
    prep(ow1, 256, 2, 256, 16, WOFF_O1);

    cudaFuncSetAttribute(fused_kernel,
                         cudaFuncAttributeMaxDynamicSharedMemorySize, SMEM_BYTES);
    fused_kernel<<<NCTA, 256, SMEM_BYTES>>>(b0, b1, b2, rb0, rb1, ob0, ob1, out);
}

// round 7
// speedup vs baseline: 2.3819x; 1.0678x over previous
#include <cuda_runtime.h>
#include <cuda_bf16.h>
#include <cstdint>

// ===========================================================================
// Problem constants (fixed: B=4, C=32, H=W=128, scale=2)
// ===========================================================================
#define Bn    4
#define Cn    32
#define Hn    128
#define Wn    128
#define QPB   65536
#define NQ    (Bn * QPB)
#define MT    32                   // queries per CTA
#define NCTA  (NQ / MT)            // 8192
#define NRB   2                    // row-blocks (16 rows) per CTA

// ===========================================================================
// Global scratch
// ===========================================================================
__device__ float g_xt[Bn * Hn * Wn * Cn];   // channels-last x

// Weight images: B-fragment-packed bf16, hi then lo (PSTR apart).
#define WOFF_L1  0u          // KC=3,  NPT=16 -> 24576
#define WOFF_L2  24576u      // KC=16, NPT=16 -> 131072
#define WOFF_L3  155648u     // KC=16, NPT=2  -> 16384
#define WOFF_R0  172032u     // KC=2,  NPT=16 -> 16384
#define WOFF_R1  188416u     // KC=16, NPT=2  -> 16384
#define WOFF_O0  204800u     // KC=2,  NPT=16 -> 16384
#define WOFF_O1  221184u     // KC=16, NPT=1  -> 8192
#define PSTR     229376u
__device__ __align__(16) unsigned char g_wimg[2 * PSTR];

// ===========================================================================
// Transpose kernel: x[B,C,H,W] -> g_xt[B,H,W,C]
// ===========================================================================
__global__ void xt_kernel(const float* __restrict__ x) {
    __shared__ float s[Cn][Wn + 1];
    const int by = blockIdx.x;
    const int tid = threadIdx.x;
#pragma unroll
    for (int it = 0; it < 16; ++it) {
        int idx = tid + it * 256;
        int c = idx >> 7, xc = idx & 127;
        int b = by >> 7, y = by & 127;
        s[c][xc] = x[((b * Cn + c) * Hn + y) * Wn + xc];
    }
    __syncthreads();
#pragma unroll
    for (int it = 0; it < 16; ++it) {
        int idx = tid + it * 256;
        int xc = idx >> 5, c = idx & 31;
        g_xt[(by * Wn + xc) * Cn + c] = s[c][xc];
    }
}

// ===========================================================================
// Combined weight prep (ONE launch for all 7 layers; gridDim.y = layer).
// W fp32 [Kdim][Ndim] -> B-fragment bf16 hi/lo images.
// ===========================================================================
__global__ void prep_all(const float* __restrict__ w0, const float* __restrict__ w1,
                         const float* __restrict__ w2, const float* __restrict__ rw0,
                         const float* __restrict__ rw1, const float* __restrict__ ow0,
                         const float* __restrict__ ow1) {
    const float* W;
    int Kdim, Ndim, Kt, Nt;
    uint32_t dstOff;
    switch (blockIdx.y) {
        case 0: W = w0;  Kdim = 36;  Ndim = 256; Kt = 48;  Nt = 256; dstOff = WOFF_L1; break;
        case 1: W = w1;  Kdim = 256; Ndim = 256; Kt = 256; Nt = 256; dstOff = WOFF_L2; break;
        case 2: W = w2;  Kdim = 256; Ndim = 32;  Kt = 256; Nt = 32;  dstOff = WOFF_L3; break;
        case 3: W = rw0; Kdim = 32;  Ndim = 256; Kt = 32;  Nt = 256; dstOff = WOFF_R0; break;
        case 4: W = rw1; Kdim = 256; Ndim = 32;  Kt = 256; Nt = 32;  dstOff = WOFF_R1; break;
        case 5: W = ow0; Kdim = 32;  Ndim = 256; Kt = 32;  Nt = 256; dstOff = WOFF_O0; break;
        default: W = ow1; Kdim = 256; Ndim = 2;  Kt = 256; Nt = 16;  dstOff = WOFF_O1; break;
    }
    int idx = blockIdx.x * 256 + threadIdx.x;
    if (idx >= Kt * Nt) return;
    int k = idx / Nt;
    int n = idx % Nt;
    float w = (k < Kdim && n < Ndim) ? W[k * Ndim + n] : 0.0f;
    __nv_bfloat16 hb = __float2bfloat16(w);
    float hf = __bfloat162float(hb);
    __nv_bfloat16 lb = __float2bfloat16(w - hf);
    int kc = k >> 4, ki = k & 15;
    int nc = n >> 3, ni = n & 7;
    int npair = nc >> 1;
    int lane = ni * 4 + ((ki & 7) >> 1);
    int word = (ki >> 3) + (nc & 1) * 2;
    int half = ki & 1;
    uint32_t off = (uint32_t)(((kc * (Nt >> 4) + npair) * 32 + lane) * 16 +
                              word * 4 + half * 2);
    *reinterpret_cast<unsigned short*>(g_wimg + dstOff + off) =
        *reinterpret_cast<unsigned short*>(&hb);
    *reinterpret_cast<unsigned short*>(g_wimg + dstOff + PSTR + off) =
        *reinterpret_cast<unsigned short*>(&lb);
}

// ===========================================================================
// Bicubic helpers (torch aten, A=-0.75)
// ===========================================================================
__device__ __forceinline__ void prep_axis(float g, int& i0, float w[4]) {
    float p = ((g + 1.0f) * 128.0f - 1.0f) * 0.5f;
    float fp = floorf(p);
    i0 = (int)fp;
    float t = p - fp;
    const float A = -0.75f;
    float xx = t + 1.0f;
    w[0] = ((A * xx - 5.0f * A) * xx + 8.0f * A) * xx - 4.0f * A;
    w[1] = ((A + 2.0f) * t - (A + 3.0f)) * t * t + 1.0f;
    float s = 1.0f - t;
    w[2] = ((A + 2.0f) * s - (A + 3.0f)) * s * s + 1.0f;
    w[3] = 1.0f - w[0] - w[1] - w[2];
}

__device__ __forceinline__ float sample_c(const float* __restrict__ xb, int lane,
                                          int ix0, int iy0,
                                          const float* wx, const float* wy) {
    float acc = 0.0f;
#pragma unroll
    for (int i = 0; i < 4; ++i) {
        int yi = iy0 - 1 + i;
        if ((unsigned)yi < 128u) {
            const float* rp = xb + yi * (Wn * Cn) + lane;
            float r = 0.0f;
#pragma unroll
            for (int j = 0; j < 4; ++j) {
                int xj = ix0 - 1 + j;
                if ((unsigned)xj < 128u) r = fmaf(wx[j], __ldg(rp + xj * Cn), r);
            }
            acc = fmaf(wy[i], r, acc);
        }
    }
    return acc;
}

// bf16 split + pack (v1 in high half, v0 in low half)
__device__ __forceinline__ void split_pack(float v0, float v1,
                                           uint32_t& hw, uint32_t& lw) {
    __nv_bfloat16 h0 = __float2bfloat16(v0);
    __nv_bfloat16 h1 = __float2bfloat16(v1);
    float f0 = __bfloat162float(h0), f1 = __bfloat162float(h1);
    __nv_bfloat16 l0 = __float2bfloat16(v0 - f0);
    __nv_bfloat16 l1 = __float2bfloat16(v1 - f1);
    unsigned short uh0 = *reinterpret_cast<unsigned short*>(&h0);
    unsigned short uh1 = *reinterpret_cast<unsigned short*>(&h1);
    unsigned short ul0 = *reinterpret_cast<unsigned short*>(&l0);
    unsigned short ul1 = *reinterpret_cast<unsigned short*>(&l1);
    hw = ((uint32_t)uh1 << 16) | uh0;
    lw = ((uint32_t)ul1 << 16) | ul0;
}

// ===========================================================================
// mma.sync m16n8k16 bf16
// ===========================================================================
__device__ __forceinline__ void mma_bf16(float* c, const uint4& a,
                                         uint32_t b0, uint32_t b1) {
    asm("mma.sync.aligned.m16n8k16.row.col.f32.bf16.bf16.f32 "
        "{%0,%1,%2,%3},{%4,%5,%6,%7},{%8,%9},{%0,%1,%2,%3};"
        : "+f"(c[0]), "+f"(c[1]), "+f"(c[2]), "+f"(c[3])
        : "r"(a.x), "r"(a.y), "r"(a.z), "r"(a.w), "r"(b0), "r"(b1));
}

// K-loop over one 16-row block: C += Ah*Bh + Al*Bh + Ah*Bl.
// A region layout: uint4 index = (kc*NRB + rb)*32 + lane.
// B image layout:  uint4 index = (kc*NPT + npair)*32 + lane.
template <int KC, int NC, int NPT>
__device__ __forceinline__ void mma_layer(const uint4* __restrict__ aHi,
                                          const uint4* __restrict__ aLo,
                                          const uint4* __restrict__ bHi,
                                          const uint4* __restrict__ bLo,
                                          int rb, int nc0, float C[NC][4]) {
    const int lane = threadIdx.x & 31;
#pragma unroll
    for (int j = 0; j < NC; ++j)
#pragma unroll
        for (int t = 0; t < 4; ++t) C[j][t] = 0.0f;
    const int npair0 = nc0 >> 1;
#pragma unroll 1
    for (int kc = 0; kc < KC; ++kc) {
        uint4 ah = aHi[(kc * NRB + rb) * 32 + lane];
        uint4 al = aLo[(kc * NRB + rb) * 32 + lane];
#pragma unroll
        for (int p = 0; p < NC / 2; ++p) {
            uint4 bh = __ldg(bHi + (kc * NPT + npair0 + p) * 32 + lane);
            uint4 bl = __ldg(bLo + (kc * NPT + npair0 + p) * 32 + lane);
            mma_bf16(C[2 * p], ah, bh.x, bh.y);
            mma_bf16(C[2 * p + 1], ah, bh.z, bh.w);
            mma_bf16(C[2 * p], al, bh.x, bh.y);
            mma_bf16(C[2 * p + 1], al, bh.z, bh.w);
            mma_bf16(C[2 * p], ah, bl.x, bl.y);
            mma_bf16(C[2 * p + 1], ah, bl.z, bl.w);
        }
    }
}

// Epilogue: bias(+ReLU), split to bf16 hi/lo A fragments for the next layer.
template <int NC, bool RELU>
__device__ __forceinline__ void epi_region(float C[NC][4],
                                           const float* __restrict__ biasp,
                                           int rb, int nc0,
                                           uint32_t* dHi, uint32_t* dLo) {
    const int lane = threadIdx.x & 31;
    const int q = (lane & 3) * 2;
#pragma unroll
    for (int j = 0; j < NC; ++j) {
        int nc = nc0 + j;
        int kc = nc >> 1, odd = nc & 1;
        float b0 = __ldg(biasp + nc * 8 + q);
        float b1 = __ldg(biasp + nc * 8 + q + 1);
        float v0 = C[j][0] + b0, v1 = C[j][1] + b1;
        float v2 = C[j][2] + b0, v3 = C[j][3] + b1;
        if (RELU) {
            v0 = fmaxf(v0, 0.f); v1 = fmaxf(v1, 0.f);
            v2 = fmaxf(v2, 0.f); v3 = fmaxf(v3, 0.f);
        }
        uint32_t h01, l01, h23, l23;
        split_pack(v0, v1, h01, l01);
        split_pack(v2, v3, h23, l23);
        int base = ((kc * NRB + rb) * 32 + lane) * 4 + odd * 2;
        dHi[base] = h01; dHi[base + 1] = h23;
        dLo[base] = l01; dLo[base + 1] = l23;
    }
}

// ===========================================================================
// SMEM layout (bytes) — total 53760 -> 4 CTAs/SM
// ===========================================================================
#define SM_INPF  0          // fp32 [32][49] = 6272 (reused as routs [32][33])
#define SM_SHI   6272       // inp frags hi: 3*2*512 = 3072
#define SM_SLO   9344
#define SM_PHI   12416      // pred frags hi: 2*2*512 = 2048
#define SM_PLO   14464
#define SM_AHI   16512      // act frags hi: 16*2*512 = 16384
#define SM_ALO   32896
#define SM_OFFS  49280      // fp32 [32][2] = 256
#define SM_OUT   49536      // fp32 [32][33] = 4224
#define SMEM_BYTES 53760

// ===========================================================================
// Fused kernel: 32 queries per CTA, 8 warps, 4 CTAs/SM.
// Warp tile: rb = wid&1 (16 rows), nq = wid>>1 (64 of 256 N cols).
// ===========================================================================
__global__ __launch_bounds__(256, 4) void fused_kernel(
    const float* __restrict__ b0p, const float* __restrict__ b1p,
    const float* __restrict__ b2p, const float* __restrict__ rb0p,
    const float* __restrict__ rb1p, const float* __restrict__ ob0p,
    const float* __restrict__ ob1p, float* __restrict__ out) {
    extern __shared__ __align__(16) unsigned char smraw[];
    float* inpF = reinterpret_cast<float*>(smraw + SM_INPF);
    uint4* SHi = reinterpret_cast<uint4*>(smraw + SM_SHI);
    uint4* SLo = reinterpret_cast<uint4*>(smraw + SM_SLO);
    uint4* PHi = reinterpret_cast<uint4*>(smraw + SM_PHI);
    uint4* PLo = reinterpret_cast<uint4*>(smraw + SM_PLO);
    uint4* AHi = reinterpret_cast<uint4*>(smraw + SM_AHI);
    uint4* ALo = reinterpret_cast<uint4*>(smraw + SM_ALO);
    uint32_t* PHiW = reinterpret_cast<uint32_t*>(PHi);
    uint32_t* PLoW = reinterpret_cast<uint32_t*>(PLo);
    uint32_t* AHiW = reinterpret_cast<uint32_t*>(AHi);
    uint32_t* ALoW = reinterpret_cast<uint32_t*>(ALo);
    float* offs  = reinterpret_cast<float*>(smraw + SM_OFFS);
    float* outst = reinterpret_cast<float*>(smraw + SM_OUT);
    float* routs = inpF;   // reuse after L1 staging

    const int tid = threadIdx.x;
    const int lane = tid & 31;
    const int wid = tid >> 5;
    const int rb = wid & 1;
    const int nq = wid >> 1;          // 0..3, 64 N-cols each

    const int q0 = blockIdx.x * MT;
    const int b = q0 >> 16;
    const int qbase = q0 & (QPB - 1);
    const float* xb = g_xt + b * (Hn * Wn * Cn);

    const uint4* WL1H = (const uint4*)(g_wimg + WOFF_L1);
    const uint4* WL1L = (const uint4*)(g_wimg + WOFF_L1 + PSTR);
    const uint4* WL2H = (const uint4*)(g_wimg + WOFF_L2);
    const uint4* WL2L = (const uint4*)(g_wimg + WOFF_L2 + PSTR);
    const uint4* WL3H = (const uint4*)(g_wimg + WOFF_L3);
    const uint4* WL3L = (const uint4*)(g_wimg + WOFF_L3 + PSTR);
    const uint4* WR0H = (const uint4*)(g_wimg + WOFF_R0);
    const uint4* WR0L = (const uint4*)(g_wimg + WOFF_R0 + PSTR);
    const uint4* WR1H = (const uint4*)(g_wimg + WOFF_R1);
    const uint4* WR1L = (const uint4*)(g_wimg + WOFF_R1 + PSTR);
    const uint4* WO0H = (const uint4*)(g_wimg + WOFF_O0);
    const uint4* WO0L = (const uint4*)(g_wimg + WOFF_O0 + PSTR);
    const uint4* WO1H = (const uint4*)(g_wimg + WOFF_O1);
    const uint4* WO1L = (const uint4*)(g_wimg + WOFF_O1 + PSTR);

    // ---- Stage A: sampling -> inpF [32][49] --------------------------------
#pragma unroll 1
    for (int i = 0; i < 4; ++i) {
        int m = wid * 4 + i;
        int ql = qbase + m;
        int oy = ql >> 8, ox = ql & 255;
        float gy = (2.0f * oy + 1.0f) * (1.0f / 256.0f) - 1.0f;
        float gx = (2.0f * ox + 1.0f) * (1.0f / 256.0f) - 1.0f;
        int ix0, iy0;
        float wx[4], wy[4];
        prep_axis(gx, ix0, wx);
        prep_axis(gy, iy0, wy);
        inpF[m * 49 + lane] = sample_c(xb, lane, ix0, iy0, wx, wy);
        if (lane == 0) {
            float syw = 0.f, sy = 0.f, sxw = 0.f, sx = 0.f;
#pragma unroll
            for (int ii = 0; ii < 4; ++ii) {
                int yi = iy0 - 1 + ii;
                if ((unsigned)yi < 128u) {
                    float yco = (2.0f * yi + 1.0f) * (1.0f / 128.0f) - 1.0f;
                    syw += wy[ii]; sy = fmaf(wy[ii], yco, sy);
                }
            }
#pragma unroll
            for (int jj = 0; jj < 4; ++jj) {
                int xj = ix0 - 1 + jj;
                if ((unsigned)xj < 128u) {
                    float xco = (2.0f * xj + 1.0f) * (1.0f / 128.0f) - 1.0f;
                    sxw += wx[jj]; sx = fmaf(wx[jj], xco, sx);
                }
            }
            inpF[m * 49 + 32] = (gy - sy * sxw) * 128.0f;
            inpF[m * 49 + 33] = (gx - sx * syw) * 128.0f;
            float rc = (ql < 2) ? 1.0f : 128.0f;   // faithful cell quirk
            inpF[m * 49 + 34] = rc;
            inpF[m * 49 + 35] = rc;
        }
        if (lane >= 4 && lane < 16) inpF[m * 49 + 32 + lane] = 0.0f;  // pad 36..47
    }
    __syncthreads();

    // ---- Stage S frags: inpF -> S (A-fragment bf16 hi/lo, K=48) -------------
    // 6 (kc, rb) combos over 8 warps
    if (wid < 6) {
        int kc = wid >> 1, rbs = wid & 1;
        int r0 = rbs * 16 + (lane >> 2);
        int k0 = kc * 16 + (lane & 3) * 2;
        float v00 = inpF[r0 * 49 + k0],       v01 = inpF[r0 * 49 + k0 + 1];
        float v10 = inpF[(r0 + 8) * 49 + k0], v11 = inpF[(r0 + 8) * 49 + k0 + 1];
        float v02 = inpF[r0 * 49 + k0 + 8],   v03 = inpF[r0 * 49 + k0 + 9];
        float v12 = inpF[(r0 + 8) * 49 + k0 + 8], v13 = inpF[(r0 + 8) * 49 + k0 + 9];
        uint4 hi, lo;
        split_pack(v00, v01, hi.x, lo.x);
        split_pack(v10, v11, hi.y, lo.y);
        split_pack(v02, v03, hi.z, lo.z);
        split_pack(v12, v13, hi.w, lo.w);
        SHi[(kc * NRB + rbs) * 32 + lane] = hi;
        SLo[(kc * NRB + rbs) * 32 + lane] = lo;
    }
    __syncthreads();

    float C8[8][4];
    float C2[2][4];

    // ---- L1: S(K=48) x W0 -> h1 (N=256) -> A --------------------------------
    mma_layer<3, 8, 16>(SHi, SLo, WL1H, WL1L, rb, nq * 8, C8);
    epi_region<8, true>(C8, b0p, rb, nq * 8, AHiW, ALoW);
    __syncthreads();

    // ---- L2: A(K=256) x W1 -> h2 (N=256) -> A (in place) --------------------
    mma_layer<16, 8, 16>(AHi, ALo, WL2H, WL2L, rb, nq * 8, C8);
    __syncthreads();   // all reads of A done before overwriting
    epi_region<8, true>(C8, b1p, rb, nq * 8, AHiW, ALoW);
    __syncthreads();

    // ---- L3: A(K=256) x W2 -> pred (N=32, no relu) -> P ----------------------
    if (nq < 2) {
        mma_layer<16, 2, 2>(AHi, ALo, WL3H, WL3L, rb, nq * 2, C2);
        epi_region<2, false>(C2, b2p, rb, nq * 2, PHiW, PLoW);
    }
    __syncthreads();

    // ---- O0: P(K=32) x OW0 -> off-hidden (N=256) -> A ------------------------
    mma_layer<2, 8, 16>(PHi, PLo, WO0H, WO0L, rb, nq * 8, C8);
    epi_region<8, true>(C8, ob0p, rb, nq * 8, AHiW, ALoW);
    __syncthreads();

    // ---- O1: A(K=256) x OW1 -> offsets (cols 0,1) ----------------------------
    if (nq == 0) {
        mma_layer<16, 2, 1>(AHi, ALo, WO1H, WO1L, rb, 0, C2);
        if ((lane & 3) == 0) {
            float o0 = __ldg(ob1p + 0), o1 = __ldg(ob1p + 1);
            int row = rb * 16 + (lane >> 2);
            offs[row * 2 + 0] = C2[0][0] + o0;
            offs[row * 2 + 1] = C2[0][1] + o1;
            offs[(row + 8) * 2 + 0] = C2[0][2] + o0;
            offs[(row + 8) * 2 + 1] = C2[0][3] + o1;
        }
    }
    __syncthreads();

    // ---- R0: P(K=32) x RW0 -> rout-hidden (N=256) -> A ------------------------
    mma_layer<2, 8, 16>(PHi, PLo, WR0H, WR0L, rb, nq * 8, C8);
    epi_region<8, true>(C8, rb0p, rb, nq * 8, AHiW, ALoW);
    __syncthreads();

    // ---- R1: A(K=256) x RW1 -> routing (N=32) -> routs fp32 -------------------
    if (nq < 2) mma_layer<16, 2, 2>(AHi, ALo, WR1H, WR1L, rb, nq * 2, C2);
    __syncthreads();   // A reads done; routs aliases inpF
    if (nq < 2) {
        const int q = (lane & 3) * 2;
#pragma unroll
        for (int j = 0; j < 2; ++j) {
            int nc = nq * 2 + j;
            float bb0 = __ldg(rb1p + nc * 8 + q);
            float bb1 = __ldg(rb1p + nc * 8 + q + 1);
            int row = rb * 16 + (lane >> 2);
            routs[row * 33 + nc * 8 + q]     = C2[j][0] + bb0;
            routs[row * 33 + nc * 8 + q + 1] = C2[j][1] + bb1;
            routs[(row + 8) * 33 + nc * 8 + q]     = C2[j][2] + bb0;
            routs[(row + 8) * 33 + nc * 8 + q + 1] = C2[j][3] + bb1;
        }
    }
    __syncthreads();

    // ---- Stage C: offset resample + modulate ---------------------------------
#pragma unroll 1
    for (int i = 0; i < 4; ++i) {
        int m = wid * 4 + i;
        int ql = qbase + m;
        int oy = ql >> 8, ox = ql & 255;
        float gy = (2.0f * oy + 1.0f) * (1.0f / 256.0f) - 1.0f;
        float gx = (2.0f * ox + 1.0f) * (1.0f / 256.0f) - 1.0f;
        float gx2 = gx + offs[m * 2 + 0];
        float gy2 = gy + offs[m * 2 + 1];
        int ix0, iy0;
        float wx[4], wy[4];
        prep_axis(gx2, ix0, wx);
        prep_axis(gy2, iy0, wy);
        float v = sample_c(xb, lane, ix0, iy0, wx, wy);
        outst[lane * 33 + m] = v * (1.0f + routs[m * 33 + lane]);
    }
    __syncthreads();

    // ---- writeout -------------------------------------------------------------
    {
        int c = tid >> 3;
        int part = tid & 7;
        const float* src = outst + c * 33 + part * 4;
        float* dst = out + ((size_t)(b * Cn + c)) * QPB + qbase + part * 4;
        *reinterpret_cast<float4*>(dst) =
            make_float4(src[0], src[1], src[2], src[3]);
    }
}

// ===========================================================================
// kernel_launch — 3 launches: xt, prep_all, fused
// ===========================================================================
extern "C" void kernel_launch(void* const* d_in, const int* in_sizes, int n_in,
                              void* d_out, int out_size) {
    const float* x   = (const float*)d_in[0];
    const float* w0  = (const float*)d_in[1];
    const float* b0  = (const float*)d_in[2];
    const float* w1  = (const float*)d_in[3];
    const float* b1  = (const float*)d_in[4];
    const float* w2  = (const float*)d_in[5];
    const float* b2  = (const float*)d_in[6];
    const float* rw0 = (const float*)d_in[7];
    const float* rb0 = (const float*)d_in[8];
    const float* rw1 = (const float*)d_in[9];
    const float* rb1 = (const float*)d_in[10];
    const float* ow0 = (const float*)d_in[11];
    const float* ob0 = (const float*)d_in[12];
    const float* ow1 = (const float*)d_in[13];
    const float* ob1 = (const float*)d_in[14];
    float* out = (float*)d_out;

    xt_kernel<<<Bn * Hn, 256>>>(x);
    prep_all<<<dim3(256, 7), 256>>>(w0, w1, w2, rw0, rw1, ow0, ow1);

    cudaFuncSetAttribute(fused_kernel,
                         cudaFuncAttributeMaxDynamicSharedMemorySize, SMEM_BYTES);
    fused_kernel<<<NCTA, 256, SMEM_BYTES>>>(b0, b1, b2, rb0, rb1, ob0, ob1, out);
}

// round 8
// speedup vs baseline: 2.5641x; 1.0765x over previous
#include <cuda_runtime.h>
#include <cuda_bf16.h>
#include <cstdint>

// ===========================================================================
// Problem constants (fixed: B=4, C=32, H=W=128, scale=2)
// ===========================================================================
#define Bn    4
#define Cn    32
#define Hn    128
#define Wn    128
#define QPB   65536
#define NQ    (Bn * QPB)
#define MT    32                   // queries per CTA
#define NCTA  (NQ / MT)            // 8192
#define NRB   2                    // row-blocks (16 rows) per CTA

// ===========================================================================
// Global scratch
// ===========================================================================
__device__ float g_xt[Bn * Hn * Wn * Cn];   // channels-last x

// Weight images: B-fragment-packed bf16, hi then lo (PSTR apart).
#define WOFF_L1  0u          // KC=3,  NPT=16 -> 24576
#define WOFF_L2  24576u      // KC=16, NPT=16 -> 131072
#define WOFF_L3  155648u     // KC=16, NPT=2  -> 16384
#define WOFF_R0  172032u     // KC=2,  NPT=16 -> 16384
#define WOFF_R1  188416u     // KC=16, NPT=2  -> 16384
#define WOFF_O0  204800u     // KC=2,  NPT=16 -> 16384
#define WOFF_O1  221184u     // KC=16, NPT=1  -> 8192
#define PSTR     229376u
__device__ __align__(16) unsigned char g_wimg[2 * PSTR];

// ===========================================================================
// Transpose kernel: x[B,C,H,W] -> g_xt[B,H,W,C]
// ===========================================================================
__global__ void xt_kernel(const float* __restrict__ x) {
    __shared__ float s[Cn][Wn + 1];
    const int by = blockIdx.x;
    const int tid = threadIdx.x;
#pragma unroll
    for (int it = 0; it < 16; ++it) {
        int idx = tid + it * 256;
        int c = idx >> 7, xc = idx & 127;
        int b = by >> 7, y = by & 127;
        s[c][xc] = x[((b * Cn + c) * Hn + y) * Wn + xc];
    }
    __syncthreads();
#pragma unroll
    for (int it = 0; it < 16; ++it) {
        int idx = tid + it * 256;
        int xc = idx >> 5, c = idx & 31;
        g_xt[(by * Wn + xc) * Cn + c] = s[c][xc];
    }
}

// ===========================================================================
// Combined weight prep (one launch; gridDim.y = layer).
// ===========================================================================
__global__ void prep_all(const float* __restrict__ w0, const float* __restrict__ w1,
                         const float* __restrict__ w2, const float* __restrict__ rw0,
                         const float* __restrict__ rw1, const float* __restrict__ ow0,
                         const float* __restrict__ ow1) {
    const float* W;
    int Kdim, Ndim, Kt, Nt;
    uint32_t dstOff;
    switch (blockIdx.y) {
        case 0: W = w0;  Kdim = 36;  Ndim = 256; Kt = 48;  Nt = 256; dstOff = WOFF_L1; break;
        case 1: W = w1;  Kdim = 256; Ndim = 256; Kt = 256; Nt = 256; dstOff = WOFF_L2; break;
        case 2: W = w2;  Kdim = 256; Ndim = 32;  Kt = 256; Nt = 32;  dstOff = WOFF_L3; break;
        case 3: W = rw0; Kdim = 32;  Ndim = 256; Kt = 32;  Nt = 256; dstOff = WOFF_R0; break;
        case 4: W = rw1; Kdim = 256; Ndim = 32;  Kt = 256; Nt = 32;  dstOff = WOFF_R1; break;
        case 5: W = ow0; Kdim = 32;  Ndim = 256; Kt = 32;  Nt = 256; dstOff = WOFF_O0; break;
        default: W = ow1; Kdim = 256; Ndim = 2;  Kt = 256; Nt = 16;  dstOff = WOFF_O1; break;
    }
    int idx = blockIdx.x * 256 + threadIdx.x;
    if (idx >= Kt * Nt) return;
    int k = idx / Nt;
    int n = idx % Nt;
    float w = (k < Kdim && n < Ndim) ? W[k * Ndim + n] : 0.0f;
    __nv_bfloat16 hb = __float2bfloat16(w);
    float hf = __bfloat162float(hb);
    __nv_bfloat16 lb = __float2bfloat16(w - hf);
    int kc = k >> 4, ki = k & 15;
    int nc = n >> 3, ni = n & 7;
    int npair = nc >> 1;
    int lane = ni * 4 + ((ki & 7) >> 1);
    int word = (ki >> 3) + (nc & 1) * 2;
    int half = ki & 1;
    uint32_t off = (uint32_t)(((kc * (Nt >> 4) + npair) * 32 + lane) * 16 +
                              word * 4 + half * 2);
    *reinterpret_cast<unsigned short*>(g_wimg + dstOff + off) =
        *reinterpret_cast<unsigned short*>(&hb);
    *reinterpret_cast<unsigned short*>(g_wimg + dstOff + PSTR + off) =
        *reinterpret_cast<unsigned short*>(&lb);
}

// ===========================================================================
// Bicubic helpers (torch aten, A=-0.75)
// ===========================================================================
__device__ __forceinline__ void prep_axis(float g, int& i0, float w[4]) {
    float p = ((g + 1.0f) * 128.0f - 1.0f) * 0.5f;
    float fp = floorf(p);
    i0 = (int)fp;
    float t = p - fp;
    const float A = -0.75f;
    float xx = t + 1.0f;
    w[0] = ((A * xx - 5.0f * A) * xx + 8.0f * A) * xx - 4.0f * A;
    w[1] = ((A + 2.0f) * t - (A + 3.0f)) * t * t + 1.0f;
    float s = 1.0f - t;
    w[2] = ((A + 2.0f) * s - (A + 3.0f)) * s * s + 1.0f;
    w[3] = 1.0f - w[0] - w[1] - w[2];
}

__device__ __forceinline__ float sample_c(const float* __restrict__ xb, int lane,
                                          int ix0, int iy0,
                                          const float* wx, const float* wy) {
    float acc = 0.0f;
#pragma unroll
    for (int i = 0; i < 4; ++i) {
        int yi = iy0 - 1 + i;
        if ((unsigned)yi < 128u) {
            const float* rp = xb + yi * (Wn * Cn) + lane;
            float r = 0.0f;
#pragma unroll
            for (int j = 0; j < 4; ++j) {
                int xj = ix0 - 1 + j;
                if ((unsigned)xj < 128u) r = fmaf(wx[j], __ldg(rp + xj * Cn), r);
            }
            acc = fmaf(wy[i], r, acc);
        }
    }
    return acc;
}

// bf16 split + pack (v1 in high half, v0 in low half)
__device__ __forceinline__ void split_pack(float v0, float v1,
                                           uint32_t& hw, uint32_t& lw) {
    __nv_bfloat16 h0 = __float2bfloat16(v0);
    __nv_bfloat16 h1 = __float2bfloat16(v1);
    float f0 = __bfloat162float(h0), f1 = __bfloat162float(h1);
    __nv_bfloat16 l0 = __float2bfloat16(v0 - f0);
    __nv_bfloat16 l1 = __float2bfloat16(v1 - f1);
    unsigned short uh0 = *reinterpret_cast<unsigned short*>(&h0);
    unsigned short uh1 = *reinterpret_cast<unsigned short*>(&h1);
    unsigned short ul0 = *reinterpret_cast<unsigned short*>(&l0);
    unsigned short ul1 = *reinterpret_cast<unsigned short*>(&l1);
    hw = ((uint32_t)uh1 << 16) | uh0;
    lw = ((uint32_t)ul1 << 16) | ul0;
}

// ===========================================================================
// mma.sync m16n8k16 bf16
// ===========================================================================
__device__ __forceinline__ void mma_bf16(float* c, const uint4& a,
                                         uint32_t b0, uint32_t b1) {
    asm("mma.sync.aligned.m16n8k16.row.col.f32.bf16.bf16.f32 "
        "{%0,%1,%2,%3},{%4,%5,%6,%7},{%8,%9},{%0,%1,%2,%3};"
        : "+f"(c[0]), "+f"(c[1]), "+f"(c[2]), "+f"(c[3])
        : "r"(a.x), "r"(a.y), "r"(a.z), "r"(a.w), "r"(b0), "r"(b1));
}

// K-loop over BOTH 16-row blocks: C += Ah*Bh + Al*Bh + Ah*Bl.
// Each warp owns a UNIQUE N-slice -> weight LDG not duplicated across warps.
// A region layout: uint4 index = (kc*NRB + rb)*32 + lane.
// B image layout:  uint4 index = (kc*NPT + npair)*32 + lane.
template <int KC, int NC, int NPT>
__device__ __forceinline__ void mma_layer(const uint4* __restrict__ aHi,
                                          const uint4* __restrict__ aLo,
                                          const uint4* __restrict__ bHi,
                                          const uint4* __restrict__ bLo,
                                          int nc0, float C[2][NC][4]) {
    const int lane = threadIdx.x & 31;
#pragma unroll
    for (int r = 0; r < 2; ++r)
#pragma unroll
        for (int j = 0; j < NC; ++j)
#pragma unroll
            for (int t = 0; t < 4; ++t) C[r][j][t] = 0.0f;
    const int npair0 = nc0 >> 1;
#pragma unroll 1
    for (int kc = 0; kc < KC; ++kc) {
        uint4 ah0 = aHi[(kc * NRB + 0) * 32 + lane];
        uint4 ah1 = aHi[(kc * NRB + 1) * 32 + lane];
        uint4 al0 = aLo[(kc * NRB + 0) * 32 + lane];
        uint4 al1 = aLo[(kc * NRB + 1) * 32 + lane];
#pragma unroll
        for (int p = 0; p < NC / 2; ++p) {
            uint4 bh = __ldg(bHi + (kc * NPT + npair0 + p) * 32 + lane);
            uint4 bl = __ldg(bLo + (kc * NPT + npair0 + p) * 32 + lane);
            mma_bf16(C[0][2 * p], ah0, bh.x, bh.y);
            mma_bf16(C[1][2 * p], ah1, bh.x, bh.y);
            mma_bf16(C[0][2 * p + 1], ah0, bh.z, bh.w);
            mma_bf16(C[1][2 * p + 1], ah1, bh.z, bh.w);
            mma_bf16(C[0][2 * p], al0, bh.x, bh.y);
            mma_bf16(C[1][2 * p], al1, bh.x, bh.y);
            mma_bf16(C[0][2 * p + 1], al0, bh.z, bh.w);
            mma_bf16(C[1][2 * p + 1], al1, bh.z, bh.w);
            mma_bf16(C[0][2 * p], ah0, bl.x, bl.y);
            mma_bf16(C[1][2 * p], ah1, bl.x, bl.y);
            mma_bf16(C[0][2 * p + 1], ah0, bl.z, bl.w);
            mma_bf16(C[1][2 * p + 1], ah1, bl.z, bl.w);
        }
    }
}

// Epilogue: bias(+ReLU), split to bf16 hi/lo A fragments for the next layer.
template <int NC, bool RELU>
__device__ __forceinline__ void epi_region(float C[2][NC][4],
                                           const float* __restrict__ biasp,
                                           int nc0,
                                           uint32_t* dHi, uint32_t* dLo) {
    const int lane = threadIdx.x & 31;
    const int q = (lane & 3) * 2;
#pragma unroll
    for (int j = 0; j < NC; ++j) {
        int nc = nc0 + j;
        int kc = nc >> 1, odd = nc & 1;
        float b0 = __ldg(biasp + nc * 8 + q);
        float b1 = __ldg(biasp + nc * 8 + q + 1);
#pragma unroll
        for (int r = 0; r < 2; ++r) {
            float v0 = C[r][j][0] + b0, v1 = C[r][j][1] + b1;
            float v2 = C[r][j][2] + b0, v3 = C[r][j][3] + b1;
            if (RELU) {
                v0 = fmaxf(v0, 0.f); v1 = fmaxf(v1, 0.f);
                v2 = fmaxf(v2, 0.f); v3 = fmaxf(v3, 0.f);
            }
            uint32_t h01, l01, h23, l23;
            split_pack(v0, v1, h01, l01);
            split_pack(v2, v3, h23, l23);
            int base = ((kc * NRB + r) * 32 + lane) * 4 + odd * 2;
            dHi[base] = h01; dHi[base + 1] = h23;
            dLo[base] = l01; dLo[base + 1] = l23;
        }
    }
}

// ===========================================================================
// SMEM layout (bytes) — total 53760; 3 CTAs/SM (RF-limited)
// ===========================================================================
#define SM_INPF  0          // fp32 [32][49] = 6272 (reused as routs [32][33])
#define SM_SHI   6272       // inp frags hi: 3*2*512 = 3072
#define SM_SLO   9344
#define SM_PHI   12416      // pred frags hi: 2*2*512 = 2048
#define SM_PLO   14464
#define SM_AHI   16512      // act frags hi: 16*2*512 = 16384
#define SM_ALO   32896
#define SM_OFFS  49280      // fp32 [32][2] = 256
#define SM_OUT   49536      // fp32 [32][33] = 4224
#define SMEM_BYTES 53760

// ===========================================================================
// Fused kernel: 32 queries per CTA, 8 warps, 3 CTAs/SM.
// Warp tile: UNIQUE 32 N-cols (nq = wid), BOTH row-blocks.
// ===========================================================================
__global__ __launch_bounds__(256, 3) void fused_kernel(
    const float* __restrict__ b0p, const float* __restrict__ b1p,
    const float* __restrict__ b2p, const float* __restrict__ rb0p,
    const float* __restrict__ rb1p, const float* __restrict__ ob0p,
    const float* __restrict__ ob1p, float* __restrict__ out) {
    extern __shared__ __align__(16) unsigned char smraw[];
    float* inpF = reinterpret_cast<float*>(smraw + SM_INPF);
    uint4* SHi = reinterpret_cast<uint4*>(smraw + SM_SHI);
    uint4* SLo = reinterpret_cast<uint4*>(smraw + SM_SLO);
    uint4* PHi = reinterpret_cast<uint4*>(smraw + SM_PHI);
    uint4* PLo = reinterpret_cast<uint4*>(smraw + SM_PLO);
    uint4* AHi = reinterpret_cast<uint4*>(smraw + SM_AHI);
    uint4* ALo = reinterpret_cast<uint4*>(smraw + SM_ALO);
    uint32_t* PHiW = reinterpret_cast<uint32_t*>(PHi);
    uint32_t* PLoW = reinterpret_cast<uint32_t*>(PLo);
    uint32_t* AHiW = reinterpret_cast<uint32_t*>(AHi);
    uint32_t* ALoW = reinterpret_cast<uint32_t*>(ALo);
    float* offs  = reinterpret_cast<float*>(smraw + SM_OFFS);
    float* outst = reinterpret_cast<float*>(smraw + SM_OUT);
    float* routs = inpF;   // reuse after L1 staging

    const int tid = threadIdx.x;
    const int lane = tid & 31;
    const int wid = tid >> 5;        // = unique N-slice id (32 cols)

    const int q0 = blockIdx.x * MT;
    const int b = q0 >> 16;
    const int qbase = q0 & (QPB - 1);
    const float* xb = g_xt + b * (Hn * Wn * Cn);

    const uint4* WL1H = (const uint4*)(g_wimg + WOFF_L1);
    const uint4* WL1L = (const uint4*)(g_wimg + WOFF_L1 + PSTR);
    const uint4* WL2H = (const uint4*)(g_wimg + WOFF_L2);
    const uint4* WL2L = (const uint4*)(g_wimg + WOFF_L2 + PSTR);
    const uint4* WL3H = (const uint4*)(g_wimg + WOFF_L3);
    const uint4* WL3L = (const uint4*)(g_wimg + WOFF_L3 + PSTR);
    const uint4* WR0H = (const uint4*)(g_wimg + WOFF_R0);
    const uint4* WR0L = (const uint4*)(g_wimg + WOFF_R0 + PSTR);
    const uint4* WR1H = (const uint4*)(g_wimg + WOFF_R1);
    const uint4* WR1L = (const uint4*)(g_wimg + WOFF_R1 + PSTR);
    const uint4* WO0H = (const uint4*)(g_wimg + WOFF_O0);
    const uint4* WO0L = (const uint4*)(g_wimg + WOFF_O0 + PSTR);
    const uint4* WO1H = (const uint4*)(g_wimg + WOFF_O1);
    const uint4* WO1L = (const uint4*)(g_wimg + WOFF_O1 + PSTR);

    // ---- Stage A: sampling -> inpF [32][49] --------------------------------
#pragma unroll 1
    for (int i = 0; i < 4; ++i) {
        int m = wid * 4 + i;
        int ql = qbase + m;
        int oy = ql >> 8, ox = ql & 255;
        float gy = (2.0f * oy + 1.0f) * (1.0f / 256.0f) - 1.0f;
        float gx = (2.0f * ox + 1.0f) * (1.0f / 256.0f) - 1.0f;
        int ix0, iy0;
        float wx[4], wy[4];
        prep_axis(gx, ix0, wx);
        prep_axis(gy, iy0, wy);
        inpF[m * 49 + lane] = sample_c(xb, lane, ix0, iy0, wx, wy);
        if (lane == 0) {
            float syw = 0.f, sy = 0.f, sxw = 0.f, sx = 0.f;
#pragma unroll
            for (int ii = 0; ii < 4; ++ii) {
                int yi = iy0 - 1 + ii;
                if ((unsigned)yi < 128u) {
                    float yco = (2.0f * yi + 1.0f) * (1.0f / 128.0f) - 1.0f;
                    syw += wy[ii]; sy = fmaf(wy[ii], yco, sy);
                }
            }
#pragma unroll
            for (int jj = 0; jj < 4; ++jj) {
                int xj = ix0 - 1 + jj;
                if ((unsigned)xj < 128u) {
                    float xco = (2.0f * xj + 1.0f) * (1.0f / 128.0f) - 1.0f;
                    sxw += wx[jj]; sx = fmaf(wx[jj], xco, sx);
                }
            }
            inpF[m * 49 + 32] = (gy - sy * sxw) * 128.0f;
            inpF[m * 49 + 33] = (gx - sx * syw) * 128.0f;
            float rc = (ql < 2) ? 1.0f : 128.0f;   // faithful cell quirk
            inpF[m * 49 + 34] = rc;
            inpF[m * 49 + 35] = rc;
        }
        if (lane >= 4 && lane < 16) inpF[m * 49 + 32 + lane] = 0.0f;  // pad 36..47
    }
    __syncthreads();

    // ---- Stage S frags: inpF -> S (A-fragment bf16 hi/lo, K=48) -------------
    if (wid < 6) {
        int kc = wid >> 1, rbs = wid & 1;
        int r0 = rbs * 16 + (lane >> 2);
        int k0 = kc * 16 + (lane & 3) * 2;
        float v00 = inpF[r0 * 49 + k0],       v01 = inpF[r0 * 49 + k0 + 1];
        float v10 = inpF[(r0 + 8) * 49 + k0], v11 = inpF[(r0 + 8) * 49 + k0 + 1];
        float v02 = inpF[r0 * 49 + k0 + 8],   v03 = inpF[r0 * 49 + k0 + 9];
        float v12 = inpF[(r0 + 8) * 49 + k0 + 8], v13 = inpF[(r0 + 8) * 49 + k0 + 9];
        uint4 hi, lo;
        split_pack(v00, v01, hi.x, lo.x);
        split_pack(v10, v11, hi.y, lo.y);
        split_pack(v02, v03, hi.z, lo.z);
        split_pack(v12, v13, hi.w, lo.w);
        SHi[(kc * NRB + rbs) * 32 + lane] = hi;
        SLo[(kc * NRB + rbs) * 32 + lane] = lo;
    }
    __syncthreads();

    float C4[2][4][4];
    float C2[2][2][4];

    // ---- L1: S(K=48) x W0 -> h1 (N=256) -> A --------------------------------
    mma_layer<3, 4, 16>(SHi, SLo, WL1H, WL1L, wid * 4, C4);
    epi_region<4, true>(C4, b0p, wid * 4, AHiW, ALoW);
    __syncthreads();

    // ---- L2: A(K=256) x W1 -> h2 (N=256) -> A (in place) --------------------
    mma_layer<16, 4, 16>(AHi, ALo, WL2H, WL2L, wid * 4, C4);
    __syncthreads();   // all reads of A done before overwriting
    epi_region<4, true>(C4, b1p, wid * 4, AHiW, ALoW);
    __syncthreads();

    // ---- L3: A(K=256) x W2 -> pred (N=32, no relu) -> P ----------------------
    if (wid < 2) {
        mma_layer<16, 2, 2>(AHi, ALo, WL3H, WL3L, wid * 2, C2);
        epi_region<2, false>(C2, b2p, wid * 2, PHiW, PLoW);
    }
    __syncthreads();

    // ---- O0: P(K=32) x OW0 -> off-hidden (N=256) -> A ------------------------
    mma_layer<2, 4, 16>(PHi, PLo, WO0H, WO0L, wid * 4, C4);
    epi_region<4, true>(C4, ob0p, wid * 4, AHiW, ALoW);
    __syncthreads();

    // ---- O1: A(K=256) x OW1 -> offsets (cols 0,1) ----------------------------
    if (wid == 0) {
        mma_layer<16, 2, 1>(AHi, ALo, WO1H, WO1L, 0, C2);
        if ((lane & 3) == 0) {
            float o0 = __ldg(ob1p + 0), o1 = __ldg(ob1p + 1);
#pragma unroll
            for (int r = 0; r < 2; ++r) {
                int row = r * 16 + (lane >> 2);
                offs[row * 2 + 0] = C2[r][0][0] + o0;
                offs[row * 2 + 1] = C2[r][0][1] + o1;
                offs[(row + 8) * 2 + 0] = C2[r][0][2] + o0;
                offs[(row + 8) * 2 + 1] = C2[r][0][3] + o1;
            }
        }
    }
    __syncthreads();

    // ---- R0: P(K=32) x RW0 -> rout-hidden (N=256) -> A ------------------------
    mma_layer<2, 4, 16>(PHi, PLo, WR0H, WR0L, wid * 4, C4);
    epi_region<4, true>(C4, rb0p, wid * 4, AHiW, ALoW);
    __syncthreads();

    // ---- R1: A(K=256) x RW1 -> routing (N=32) -> routs fp32 -------------------
    if (wid < 2) mma_layer<16, 2, 2>(AHi, ALo, WR1H, WR1L, wid * 2, C2);
    __syncthreads();   // A reads done; routs aliases inpF
    if (wid < 2) {
        const int q = (lane & 3) * 2;
#pragma unroll
        for (int j = 0; j < 2; ++j) {
            int nc = wid * 2 + j;
            float bb0 = __ldg(rb1p + nc * 8 + q);
            float bb1 = __ldg(rb1p + nc * 8 + q + 1);
#pragma unroll
            for (int r = 0; r < 2; ++r) {
                int row = r * 16 + (lane >> 2);
                routs[row * 33 + nc * 8 + q]     = C2[r][j][0] + bb0;
                routs[row * 33 + nc * 8 + q + 1] = C2[r][j][1] + bb1;
                routs[(row + 8) * 33 + nc * 8 + q]     = C2[r][j][2] + bb0;
                routs[(row + 8) * 33 + nc * 8 + q + 1] = C2[r][j][3] + bb1;
            }
        }
    }
    __syncthreads();

    // ---- Stage C: offset resample + modulate ---------------------------------
#pragma unroll 1
    for (int i = 0; i < 4; ++i) {
        int m = wid * 4 + i;
        int ql = qbase + m;
        int oy = ql >> 8, ox = ql & 255;
        float gy = (2.0f * oy + 1.0f) * (1.0f / 256.0f) - 1.0f;
        float gx = (2.0f * ox + 1.0f) * (1.0f / 256.0f) - 1.0f;
        float gx2 = gx + offs[m * 2 + 0];
        float gy2 = gy + offs[m * 2 + 1];
        int ix0, iy0;
        float wx[4], wy[4];
        prep_axis(gx2, ix0, wx);
        prep_axis(gy2, iy0, wy);
        float v = sample_c(xb, lane, ix0, iy0, wx, wy);
        outst[lane * 33 + m] = v * (1.0f + routs[m * 33 + lane]);
    }
    __syncthreads();

    // ---- writeout -------------------------------------------------------------
    {
        int c = tid >> 3;
        int part = tid & 7;
        const float* src = outst + c * 33 + part * 4;
        float* dst = out + ((size_t)(b * Cn + c)) * QPB + qbase + part * 4;
        *reinterpret_cast<float4*>(dst) =
            make_float4(src[0], src[1], src[2], src[3]);
    }
}

// ===========================================================================
// kernel_launch — 3 launches: xt, prep_all, fused
// ===========================================================================
extern "C" void kernel_launch(void* const* d_in, const int* in_sizes, int n_in,
                              void* d_out, int out_size) {
    const float* x   = (const float*)d_in[0];
    const float* w0  = (const float*)d_in[1];
    const float* b0  = (const float*)d_in[2];
    const float* w1  = (const float*)d_in[3];
    const float* b1  = (const float*)d_in[4];
    const float* w2  = (const float*)d_in[5];
    const float* b2  = (const float*)d_in[6];
    const float* rw0 = (const float*)d_in[7];
    const float* rb0 = (const float*)d_in[8];
    const float* rw1 = (const float*)d_in[9];
    const float* rb1 = (const float*)d_in[10];
    const float* ow0 = (const float*)d_in[11];
    const float* ob0 = (const float*)d_in[12];
    const float* ow1 = (const float*)d_in[13];
    const float* ob1 = (const float*)d_in[14];
    float* out = (float*)d_out;

    xt_kernel<<<Bn * Hn, 256>>>(x);
    prep_all<<<dim3(256, 7), 256>>>(w0, w1, w2, rw0, rw1, ow0, ow1);

    cudaFuncSetAttribute(fused_kernel,
                         cudaFuncAttributeMaxDynamicSharedMemorySize, SMEM_BYTES);
    fused_kernel<<<NCTA, 256, SMEM_BYTES>>>(b0, b1, b2, rb0, rb1, ob0, ob1, out);
}

// round 9
// speedup vs baseline: 3.1558x; 1.2308x over previous
#include <cuda_runtime.h>
#include <cuda_fp16.h>
#include <cstdint>

// ===========================================================================
// Problem constants (fixed: B=4, C=32, H=W=128, scale=2)
// ===========================================================================
#define Bn    4
#define Cn    32
#define Hn    128
#define Wn    128
#define QPB   65536
#define NQ    (Bn * QPB)
#define MT    32                   // queries per CTA
#define NCTA  (NQ / MT)            // 8192
#define NRB   2                    // row-blocks (16 rows) per CTA

// ===========================================================================
// Global scratch
// ===========================================================================
__device__ float g_xt[Bn * Hn * Wn * Cn];   // channels-last x

// Weight images: B-fragment-packed fp16 (single precision level, no lo part).
#define WOFF_L1  0u          // KC=3,  NPT=16 -> 24576
#define WOFF_L2  24576u      // KC=16, NPT=16 -> 131072
#define WOFF_L3  155648u     // KC=16, NPT=2  -> 16384
#define WOFF_R0  172032u     // KC=2,  NPT=16 -> 16384
#define WOFF_R1  188416u     // KC=16, NPT=2  -> 16384
#define WOFF_O0  204800u     // KC=2,  NPT=16 -> 16384
#define WOFF_O1  221184u     // KC=16, NPT=1  -> 8192
#define WIMG_TOTAL 229376u
__device__ __align__(16) unsigned char g_wimg[WIMG_TOTAL];

// ===========================================================================
// Setup kernel: y==0 -> transpose x; y>=1 -> weight prep for layer y-1.
// ===========================================================================
__global__ void setup_kernel(const float* __restrict__ x,
                             const float* __restrict__ w0, const float* __restrict__ w1,
                             const float* __restrict__ w2, const float* __restrict__ rw0,
                             const float* __restrict__ rw1, const float* __restrict__ ow0,
                             const float* __restrict__ ow1) {
    const int tid = threadIdx.x;
    if (blockIdx.y == 0) {
        // transpose: one block per (b,y) row
        __shared__ float s[Cn][Wn + 1];
        const int by = blockIdx.x;      // 0..511
#pragma unroll
        for (int it = 0; it < 16; ++it) {
            int idx = tid + it * 256;
            int c = idx >> 7, xc = idx & 127;
            int b = by >> 7, y = by & 127;
            s[c][xc] = x[((b * Cn + c) * Hn + y) * Wn + xc];
        }
        __syncthreads();
#pragma unroll
        for (int it = 0; it < 16; ++it) {
            int idx = tid + it * 256;
            int xc = idx >> 5, c = idx & 31;
            g_xt[(by * Wn + xc) * Cn + c] = s[c][xc];
        }
        return;
    }
    // ---- weight prep ----
    const float* W;
    int Kdim, Ndim, Kt, Nt;
    uint32_t dstOff;
    switch (blockIdx.y - 1) {
        case 0: W = w0;  Kdim = 36;  Ndim = 256; Kt = 48;  Nt = 256; dstOff = WOFF_L1; break;
        case 1: W = w1;  Kdim = 256; Ndim = 256; Kt = 256; Nt = 256; dstOff = WOFF_L2; break;
        case 2: W = w2;  Kdim = 256; Ndim = 32;  Kt = 256; Nt = 32;  dstOff = WOFF_L3; break;
        case 3: W = rw0; Kdim = 32;  Ndim = 256; Kt = 32;  Nt = 256; dstOff = WOFF_R0; break;
        case 4: W = rw1; Kdim = 256; Ndim = 32;  Kt = 256; Nt = 32;  dstOff = WOFF_R1; break;
        case 5: W = ow0; Kdim = 32;  Ndim = 256; Kt = 32;  Nt = 256; dstOff = WOFF_O0; break;
        default: W = ow1; Kdim = 256; Ndim = 2;  Kt = 256; Nt = 16;  dstOff = WOFF_O1; break;
    }
    int idx = blockIdx.x * 256 + tid;
    if (idx >= Kt * Nt) return;
    int k = idx / Nt;
    int n = idx % Nt;
    float w = (k < Kdim && n < Ndim) ? W[k * Ndim + n] : 0.0f;
    __half hb = __float2half_rn(w);
    int kc = k >> 4, ki = k & 15;
    int nc = n >> 3, ni = n & 7;
    int npair = nc >> 1;
    int lane = ni * 4 + ((ki & 7) >> 1);
    int word = (ki >> 3) + (nc & 1) * 2;
    int half = ki & 1;
    uint32_t off = (uint32_t)(((kc * (Nt >> 4) + npair) * 32 + lane) * 16 +
                              word * 4 + half * 2);
    *reinterpret_cast<unsigned short*>(g_wimg + dstOff + off) = __half_as_ushort(hb);
}

// ===========================================================================
// Bicubic helpers (torch aten, A=-0.75)
// ===========================================================================
__device__ __forceinline__ void prep_axis(float g, int& i0, float w[4]) {
    float p = ((g + 1.0f) * 128.0f - 1.0f) * 0.5f;
    float fp = floorf(p);
    i0 = (int)fp;
    float t = p - fp;
    const float A = -0.75f;
    float xx = t + 1.0f;
    w[0] = ((A * xx - 5.0f * A) * xx + 8.0f * A) * xx - 4.0f * A;
    w[1] = ((A + 2.0f) * t - (A + 3.0f)) * t * t + 1.0f;
    float s = 1.0f - t;
    w[2] = ((A + 2.0f) * s - (A + 3.0f)) * s * s + 1.0f;
    w[3] = 1.0f - w[0] - w[1] - w[2];
}

__device__ __forceinline__ float sample_c(const float* __restrict__ xb, int lane,
                                          int ix0, int iy0,
                                          const float* wx, const float* wy) {
    float acc = 0.0f;
#pragma unroll
    for (int i = 0; i < 4; ++i) {
        int yi = iy0 - 1 + i;
        if ((unsigned)yi < 128u) {
            const float* rp = xb + yi * (Wn * Cn) + lane;
            float r = 0.0f;
#pragma unroll
            for (int j = 0; j < 4; ++j) {
                int xj = ix0 - 1 + j;
                if ((unsigned)xj < 128u) r = fmaf(wx[j], __ldg(rp + xj * Cn), r);
            }
            acc = fmaf(wy[i], r, acc);
        }
    }
    return acc;
}

// fp16 split + pack (v1 in high half, v0 in low half)
__device__ __forceinline__ void split_pack(float v0, float v1,
                                           uint32_t& hw, uint32_t& lw) {
    __half h0 = __float2half_rn(v0);
    __half h1 = __float2half_rn(v1);
    float f0 = __half2float(h0), f1 = __half2float(h1);
    __half l0 = __float2half_rn(v0 - f0);
    __half l1 = __float2half_rn(v1 - f1);
    hw = ((uint32_t)__half_as_ushort(h1) << 16) | __half_as_ushort(h0);
    lw = ((uint32_t)__half_as_ushort(l1) << 16) | __half_as_ushort(l0);
}

// ===========================================================================
// mma.sync m16n8k16 fp16
// ===========================================================================
__device__ __forceinline__ void mma_f16(float* c, const uint4& a,
                                        uint32_t b0, uint32_t b1) {
    asm("mma.sync.aligned.m16n8k16.row.col.f32.f16.f16.f32 "
        "{%0,%1,%2,%3},{%4,%5,%6,%7},{%8,%9},{%0,%1,%2,%3};"
        : "+f"(c[0]), "+f"(c[1]), "+f"(c[2]), "+f"(c[3])
        : "r"(a.x), "r"(a.y), "r"(a.z), "r"(a.w), "r"(b0), "r"(b1));
}

// K-loop over BOTH 16-row blocks: C += Ah*B + Al*B (A split fp16, B single fp16).
// Each warp owns a UNIQUE N-slice -> weight LDG not duplicated across warps.
// A region layout: uint4 index = (kc*NRB + rb)*32 + lane.
// B image layout:  uint4 index = (kc*NPT + npair)*32 + lane.
template <int KC, int NC, int NPT>
__device__ __forceinline__ void mma_layer(const uint4* __restrict__ aHi,
                                          const uint4* __restrict__ aLo,
                                          const uint4* __restrict__ bHi,
                                          int nc0, float C[2][NC][4]) {
    const int lane = threadIdx.x & 31;
#pragma unroll
    for (int r = 0; r < 2; ++r)
#pragma unroll
        for (int j = 0; j < NC; ++j)
#pragma unroll
            for (int t = 0; t < 4; ++t) C[r][j][t] = 0.0f;
    const int npair0 = nc0 >> 1;
#pragma unroll 1
    for (int kc = 0; kc < KC; ++kc) {
        uint4 ah0 = aHi[(kc * NRB + 0) * 32 + lane];
        uint4 ah1 = aHi[(kc * NRB + 1) * 32 + lane];
        uint4 al0 = aLo[(kc * NRB + 0) * 32 + lane];
        uint4 al1 = aLo[(kc * NRB + 1) * 32 + lane];
#pragma unroll
        for (int p = 0; p < NC / 2; ++p) {
            uint4 bh = __ldg(bHi + (kc * NPT + npair0 + p) * 32 + lane);
            mma_f16(C[0][2 * p], ah0, bh.x, bh.y);
            mma_f16(C[1][2 * p], ah1, bh.x, bh.y);
            mma_f16(C[0][2 * p + 1], ah0, bh.z, bh.w);
            mma_f16(C[1][2 * p + 1], ah1, bh.z, bh.w);
            mma_f16(C[0][2 * p], al0, bh.x, bh.y);
            mma_f16(C[1][2 * p], al1, bh.x, bh.y);
            mma_f16(C[0][2 * p + 1], al0, bh.z, bh.w);
            mma_f16(C[1][2 * p + 1], al1, bh.z, bh.w);
        }
    }
}

// Epilogue: bias(+ReLU), split to fp16 hi/lo A fragments for the next layer.
template <int NC, bool RELU>
__device__ __forceinline__ void epi_region(float C[2][NC][4],
                                           const float* __restrict__ biasp,
                                           int nc0,
                                           uint32_t* dHi, uint32_t* dLo) {
    const int lane = threadIdx.x & 31;
    const int q = (lane & 3) * 2;
#pragma unroll
    for (int j = 0; j < NC; ++j) {
        int nc = nc0 + j;
        int kc = nc >> 1, odd = nc & 1;
        float b0 = __ldg(biasp + nc * 8 + q);
        float b1 = __ldg(biasp + nc * 8 + q + 1);
#pragma unroll
        for (int r = 0; r < 2; ++r) {
            float v0 = C[r][j][0] + b0, v1 = C[r][j][1] + b1;
            float v2 = C[r][j][2] + b0, v3 = C[r][j][3] + b1;
            if (RELU) {
                v0 = fmaxf(v0, 0.f); v1 = fmaxf(v1, 0.f);
                v2 = fmaxf(v2, 0.f); v3 = fmaxf(v3, 0.f);
            }
            uint32_t h01, l01, h23, l23;
            split_pack(v0, v1, h01, l01);
            split_pack(v2, v3, h23, l23);
            int base = ((kc * NRB + r) * 32 + lane) * 4 + odd * 2;
            dHi[base] = h01; dHi[base + 1] = h23;
            dLo[base] = l01; dLo[base + 1] = l23;
        }
    }
}

// ===========================================================================
// SMEM layout (bytes) — total 53760; 3 CTAs/SM
// ===========================================================================
#define SM_INPF  0          // fp32 [32][49] = 6272 (reused as routs [32][33])
#define SM_SHI   6272       // inp frags hi: 3*2*512 = 3072
#define SM_SLO   9344
#define SM_PHI   12416      // pred frags hi: 2*2*512 = 2048
#define SM_PLO   14464
#define SM_AHI   16512      // act frags hi: 16*2*512 = 16384
#define SM_ALO   32896
#define SM_OFFS  49280      // fp32 [32][2] = 256
#define SM_OUT   49536      // fp32 [32][33] = 4224
#define SMEM_BYTES 53760

// ===========================================================================
// Fused kernel: 32 queries per CTA, 8 warps, 3 CTAs/SM.
// Warp tile: UNIQUE 32 N-cols (= wid), BOTH row-blocks.
// ===========================================================================
__global__ __launch_bounds__(256, 3) void fused_kernel(
    const float* __restrict__ b0p, const float* __restrict__ b1p,
    const float* __restrict__ b2p, const float* __restrict__ rb0p,
    const float* __restrict__ rb1p, const float* __restrict__ ob0p,
    const float* __restrict__ ob1p, float* __restrict__ out) {
    extern __shared__ __align__(16) unsigned char smraw[];
    float* inpF = reinterpret_cast<float*>(smraw + SM_INPF);
    uint4* SHi = reinterpret_cast<uint4*>(smraw + SM_SHI);
    uint4* SLo = reinterpret_cast<uint4*>(smraw + SM_SLO);
    uint4* PHi = reinterpret_cast<uint4*>(smraw + SM_PHI);
    uint4* PLo = reinterpret_cast<uint4*>(smraw + SM_PLO);
    uint4* AHi = reinterpret_cast<uint4*>(smraw + SM_AHI);
    uint4* ALo = reinterpret_cast<uint4*>(smraw + SM_ALO);
    uint32_t* PHiW = reinterpret_cast<uint32_t*>(PHi);
    uint32_t* PLoW = reinterpret_cast<uint32_t*>(PLo);
    uint32_t* AHiW = reinterpret_cast<uint32_t*>(AHi);
    uint32_t* ALoW = reinterpret_cast<uint32_t*>(ALo);
    float* offs  = reinterpret_cast<float*>(smraw + SM_OFFS);
    float* outst = reinterpret_cast<float*>(smraw + SM_OUT);
    float* routs = inpF;   // reuse after L1 staging

    const int tid = threadIdx.x;
    const int lane = tid & 31;
    const int wid = tid >> 5;        // unique N-slice id (32 cols)

    const int q0 = blockIdx.x * MT;
    const int b = q0 >> 16;
    const int qbase = q0 & (QPB - 1);
    const float* xb = g_xt + b * (Hn * Wn * Cn);

    const uint4* WL1 = (const uint4*)(g_wimg + WOFF_L1);
    const uint4* WL2 = (const uint4*)(g_wimg + WOFF_L2);
    const uint4* WL3 = (const uint4*)(g_wimg + WOFF_L3);
    const uint4* WR0 = (const uint4*)(g_wimg + WOFF_R0);
    const uint4* WR1 = (const uint4*)(g_wimg + WOFF_R1);
    const uint4* WO0 = (const uint4*)(g_wimg + WOFF_O0);
    const uint4* WO1 = (const uint4*)(g_wimg + WOFF_O1);

    // ---- Stage A: sampling -> inpF [32][49] --------------------------------
#pragma unroll 1
    for (int i = 0; i < 4; ++i) {
        int m = wid * 4 + i;
        int ql = qbase + m;
        int oy = ql >> 8, ox = ql & 255;
        float gy = (2.0f * oy + 1.0f) * (1.0f / 256.0f) - 1.0f;
        float gx = (2.0f * ox + 1.0f) * (1.0f / 256.0f) - 1.0f;
        int ix0, iy0;
        float wx[4], wy[4];
        prep_axis(gx, ix0, wx);
        prep_axis(gy, iy0, wy);
        inpF[m * 49 + lane] = sample_c(xb, lane, ix0, iy0, wx, wy);
        if (lane == 0) {
            float syw = 0.f, sy = 0.f, sxw = 0.f, sx = 0.f;
#pragma unroll
            for (int ii = 0; ii < 4; ++ii) {
                int yi = iy0 - 1 + ii;
                if ((unsigned)yi < 128u) {
                    float yco = (2.0f * yi + 1.0f) * (1.0f / 128.0f) - 1.0f;
                    syw += wy[ii]; sy = fmaf(wy[ii], yco, sy);
                }
            }
#pragma unroll
            for (int jj = 0; jj < 4; ++jj) {
                int xj = ix0 - 1 + jj;
                if ((unsigned)xj < 128u) {
                    float xco = (2.0f * xj + 1.0f) * (1.0f / 128.0f) - 1.0f;
                    sxw += wx[jj]; sx = fmaf(wx[jj], xco, sx);
                }
            }
            inpF[m * 49 + 32] = (gy - sy * sxw) * 128.0f;
            inpF[m * 49 + 33] = (gx - sx * syw) * 128.0f;
            float rc = (ql < 2) ? 1.0f : 128.0f;   // faithful cell quirk
            inpF[m * 49 + 34] = rc;
            inpF[m * 49 + 35] = rc;
        }
        if (lane >= 4 && lane < 16) inpF[m * 49 + 32 + lane] = 0.0f;  // pad 36..47
    }
    __syncthreads();

    // ---- Stage S frags: inpF -> S (A-fragment fp16 hi/lo, K=48) -------------
    if (wid < 6) {
        int kc = wid >> 1, rbs = wid & 1;
        int r0 = rbs * 16 + (lane >> 2);
        int k0 = kc * 16 + (lane & 3) * 2;
        float v00 = inpF[r0 * 49 + k0],       v01 = inpF[r0 * 49 + k0 + 1];
        float v10 = inpF[(r0 + 8) * 49 + k0], v11 = inpF[(r0 + 8) * 49 + k0 + 1];
        float v02 = inpF[r0 * 49 + k0 + 8],   v03 = inpF[r0 * 49 + k0 + 9];
        float v12 = inpF[(r0 + 8) * 49 + k0 + 8], v13 = inpF[(r0 + 8) * 49 + k0 + 9];
        uint4 hi, lo;
        split_pack(v00, v01, hi.x, lo.x);
        split_pack(v10, v11, hi.y, lo.y);
        split_pack(v02, v03, hi.z, lo.z);
        split_pack(v12, v13, hi.w, lo.w);
        SHi[(kc * NRB + rbs) * 32 + lane] = hi;
        SLo[(kc * NRB + rbs) * 32 + lane] = lo;
    }
    __syncthreads();

    float C4[2][4][4];
    float C2[2][2][4];

    // ---- L1: S(K=48) x W0 -> h1 (N=256) -> A --------------------------------
    mma_layer<3, 4, 16>(SHi, SLo, WL1, wid * 4, C4);
    epi_region<4, true>(C4, b0p, wid * 4, AHiW, ALoW);
    __syncthreads();

    // ---- L2: A(K=256) x W1 -> h2 (N=256) -> A (in place) --------------------
    mma_layer<16, 4, 16>(AHi, ALo, WL2, wid * 4, C4);
    __syncthreads();   // all reads of A done before overwriting
    epi_region<4, true>(C4, b1p, wid * 4, AHiW, ALoW);
    __syncthreads();

    // ---- L3: A(K=256) x W2 -> pred (N=32, no relu) -> P ----------------------
    if (wid < 2) {
        mma_layer<16, 2, 2>(AHi, ALo, WL3, wid * 2, C2);
        epi_region<2, false>(C2, b2p, wid * 2, PHiW, PLoW);
    }
    __syncthreads();

    // ---- O0: P(K=32) x OW0 -> off-hidden (N=256) -> A ------------------------
    mma_layer<2, 4, 16>(PHi, PLo, WO0, wid * 4, C4);
    epi_region<4, true>(C4, ob0p, wid * 4, AHiW, ALoW);
    __syncthreads();

    // ---- O1: A(K=256) x OW1 -> offsets (cols 0,1) ----------------------------
    if (wid == 0) {
        mma_layer<16, 2, 1>(AHi, ALo, WO1, 0, C2);
        if ((lane & 3) == 0) {
            float o0 = __ldg(ob1p + 0), o1 = __ldg(ob1p + 1);
#pragma unroll
            for (int r = 0; r < 2; ++r) {
                int row = r * 16 + (lane >> 2);
                offs[row * 2 + 0] = C2[r][0][0] + o0;
                offs[row * 2 + 1] = C2[r][0][1] + o1;
                offs[(row + 8) * 2 + 0] = C2[r][0][2] + o0;
                offs[(row + 8) * 2 + 1] = C2[r][0][3] + o1;
            }
        }
    }
    __syncthreads();

    // ---- R0: P(K=32) x RW0 -> rout-hidden (N=256) -> A ------------------------
    mma_layer<2, 4, 16>(PHi, PLo, WR0, wid * 4, C4);
    epi_region<4, true>(C4, rb0p, wid * 4, AHiW, ALoW);
    __syncthreads();

    // ---- R1: A(K=256) x RW1 -> routing (N=32) -> routs fp32 -------------------
    if (wid < 2) mma_layer<16, 2, 2>(AHi, ALo, WR1, wid * 2, C2);
    __syncthreads();   // A reads done; routs aliases inpF
    if (wid < 2) {
        const int q = (lane & 3) * 2;
#pragma unroll
        for (int j = 0; j < 2; ++j) {
            int nc = wid * 2 + j;
            float bb0 = __ldg(rb1p + nc * 8 + q);
            float bb1 = __ldg(rb1p + nc * 8 + q + 1);
#pragma unroll
            for (int r = 0; r < 2; ++r) {
                int row = r * 16 + (lane >> 2);
                routs[row * 33 + nc * 8 + q]     = C2[r][j][0] + bb0;
                routs[row * 33 + nc * 8 + q + 1] = C2[r][j][1] + bb1;
                routs[(row + 8) * 33 + nc * 8 + q]     = C2[r][j][2] + bb0;
                routs[(row + 8) * 33 + nc * 8 + q + 1] = C2[r][j][3] + bb1;
            }
        }
    }
    __syncthreads();

    // ---- Stage C: offset resample + modulate ---------------------------------
#pragma unroll 1
    for (int i = 0; i < 4; ++i) {
        int m = wid * 4 + i;
        int ql = qbase + m;
        int oy = ql >> 8, ox = ql & 255;
        float gy = (2.0f * oy + 1.0f) * (1.0f / 256.0f) - 1.0f;
        float gx = (2.0f * ox + 1.0f) * (1.0f / 256.0f) - 1.0f;
        float gx2 = gx + offs[m * 2 + 0];
        float gy2 = gy + offs[m * 2 + 1];
        int ix0, iy0;
        float wx[4], wy[4];
        prep_axis(gx2, ix0, wx);
        prep_axis(gy2, iy0, wy);
        float v = sample_c(xb, lane, ix0, iy0, wx, wy);
        outst[lane * 33 + m] = v * (1.0f + routs[m * 33 + lane]);
    }
    __syncthreads();

    // ---- writeout -------------------------------------------------------------
    {
        int c = tid >> 3;
        int part = tid & 7;
        const float* src = outst + c * 33 + part * 4;
        float* dst = out + ((size_t)(b * Cn + c)) * QPB + qbase + part * 4;
        *reinterpret_cast<float4*>(dst) =
            make_float4(src[0], src[1], src[2], src[3]);
    }
}

// ===========================================================================
// kernel_launch — 2 launches: setup (xt + prep), fused
// ===========================================================================
extern "C" void kernel_launch(void* const* d_in, const int* in_sizes, int n_in,
                              void* d_out, int out_size) {
    const float* x   = (const float*)d_in[0];
    const float* w0  = (const float*)d_in[1];
    const float* b0  = (const float*)d_in[2];
    const float* w1  = (const float*)d_in[3];
    const float* b1  = (const float*)d_in[4];
    const float* w2  = (const float*)d_in[5];
    const float* b2  = (const float*)d_in[6];
    const float* rw0 = (const float*)d_in[7];
    const float* rb0 = (const float*)d_in[8];
    const float* rw1 = (const float*)d_in[9];
    const float* rb1 = (const float*)d_in[10];
    const float* ow0 = (const float*)d_in[11];
    const float* ob0 = (const float*)d_in[12];
    const float* ow1 = (const float*)d_in[13];
    const float* ob1 = (const float*)d_in[14];
    float* out = (float*)d_out;

    setup_kernel<<<dim3(512, 8), 256>>>(x, w0, w1, w2, rw0, rw1, ow0, ow1);

    cudaFuncSetAttribute(fused_kernel,
                         cudaFuncAttributeMaxDynamicSharedMemorySize, SMEM_BYTES);
    fused_kernel<<<NCTA, 256, SMEM_BYTES>>>(b0, b1, b2, rb0, rb1, ob0, ob1, out);
}

// round 10
// speedup vs baseline: 3.9209x; 1.2425x over previous
#include <cuda_runtime.h>
#include <cuda_fp16.h>
#include <cstdint>

// ===========================================================================
// Problem constants (fixed: B=4, C=32, H=W=128, scale=2)
// ===========================================================================
#define Bn    4
#define Cn    32
#define Hn    128
#define Wn    128
#define QPB   65536
#define NQ    (Bn * QPB)
#define MT    32                   // queries per CTA
#define NCTA  (NQ / MT)            // 8192
#define NRB   2                    // row-blocks (16 rows) per CTA

// ===========================================================================
// Global scratch
// ===========================================================================
__device__ float g_xt[Bn * Hn * Wn * Cn];   // channels-last x

// Weight images: B-fragment-packed fp16.
#define WOFF_L1  0u          // KC=3,  NPT=16 -> 24576
#define WOFF_L2  24576u      // KC=16, NPT=16 -> 131072
#define WOFF_L3  155648u     // KC=16, NPT=2  -> 16384
#define WOFF_R0  172032u     // KC=2,  NPT=16 -> 16384
#define WOFF_R1  188416u     // KC=16, NPT=2  -> 16384
#define WOFF_O0  204800u     // KC=2,  NPT=16 -> 16384
#define WOFF_O1  221184u     // KC=16, NPT=1  -> 8192
#define WIMG_TOTAL 229376u
__device__ __align__(16) unsigned char g_wimg[WIMG_TOTAL];

// ===========================================================================
// Setup kernel: y==0 -> transpose x; y>=1 -> weight prep for layer y-1.
// ===========================================================================
__global__ void setup_kernel(const float* __restrict__ x,
                             const float* __restrict__ w0, const float* __restrict__ w1,
                             const float* __restrict__ w2, const float* __restrict__ rw0,
                             const float* __restrict__ rw1, const float* __restrict__ ow0,
                             const float* __restrict__ ow1) {
    const int tid = threadIdx.x;
    if (blockIdx.y == 0) {
        __shared__ float s[Cn][Wn + 1];
        const int by = blockIdx.x;      // 0..511
#pragma unroll
        for (int it = 0; it < 16; ++it) {
            int idx = tid + it * 256;
            int c = idx >> 7, xc = idx & 127;
            int b = by >> 7, y = by & 127;
            s[c][xc] = x[((b * Cn + c) * Hn + y) * Wn + xc];
        }
        __syncthreads();
#pragma unroll
        for (int it = 0; it < 16; ++it) {
            int idx = tid + it * 256;
            int xc = idx >> 5, c = idx & 31;
            g_xt[(by * Wn + xc) * Cn + c] = s[c][xc];
        }
        return;
    }
    const float* W;
    int Kdim, Ndim, Kt, Nt;
    uint32_t dstOff;
    switch (blockIdx.y - 1) {
        case 0: W = w0;  Kdim = 36;  Ndim = 256; Kt = 48;  Nt = 256; dstOff = WOFF_L1; break;
        case 1: W = w1;  Kdim = 256; Ndim = 256; Kt = 256; Nt = 256; dstOff = WOFF_L2; break;
        case 2: W = w2;  Kdim = 256; Ndim = 32;  Kt = 256; Nt = 32;  dstOff = WOFF_L3; break;
        case 3: W = rw0; Kdim = 32;  Ndim = 256; Kt = 32;  Nt = 256; dstOff = WOFF_R0; break;
        case 4: W = rw1; Kdim = 256; Ndim = 32;  Kt = 256; Nt = 32;  dstOff = WOFF_R1; break;
        case 5: W = ow0; Kdim = 32;  Ndim = 256; Kt = 32;  Nt = 256; dstOff = WOFF_O0; break;
        default: W = ow1; Kdim = 256; Ndim = 2;  Kt = 256; Nt = 16;  dstOff = WOFF_O1; break;
    }
    int idx = blockIdx.x * 256 + tid;
    if (idx >= Kt * Nt) return;
    int k = idx / Nt;
    int n = idx % Nt;
    float w = (k < Kdim && n < Ndim) ? W[k * Ndim + n] : 0.0f;
    __half hb = __float2half_rn(w);
    int kc = k >> 4, ki = k & 15;
    int nc = n >> 3, ni = n & 7;
    int npair = nc >> 1;
    int lane = ni * 4 + ((ki & 7) >> 1);
    int word = (ki >> 3) + (nc & 1) * 2;
    int half = ki & 1;
    uint32_t off = (uint32_t)(((kc * (Nt >> 4) + npair) * 32 + lane) * 16 +
                              word * 4 + half * 2);
    *reinterpret_cast<unsigned short*>(g_wimg + dstOff + off) = __half_as_ushort(hb);
}

// ===========================================================================
// Bicubic helpers (torch aten, A=-0.75)
// ===========================================================================
__device__ __forceinline__ void prep_axis(float g, int& i0, float w[4]) {
    float p = ((g + 1.0f) * 128.0f - 1.0f) * 0.5f;
    float fp = floorf(p);
    i0 = (int)fp;
    float t = p - fp;
    const float A = -0.75f;
    float xx = t + 1.0f;
    w[0] = ((A * xx - 5.0f * A) * xx + 8.0f * A) * xx - 4.0f * A;
    w[1] = ((A + 2.0f) * t - (A + 3.0f)) * t * t + 1.0f;
    float s = 1.0f - t;
    w[2] = ((A + 2.0f) * s - (A + 3.0f)) * s * s + 1.0f;
    w[3] = 1.0f - w[0] - w[1] - w[2];
}

__device__ __forceinline__ float sample_c(const float* __restrict__ xb, int lane,
                                          int ix0, int iy0,
                                          const float* wx, const float* wy) {
    float acc = 0.0f;
#pragma unroll
    for (int i = 0; i < 4; ++i) {
        int yi = iy0 - 1 + i;
        if ((unsigned)yi < 128u) {
            const float* rp = xb + yi * (Wn * Cn) + lane;
            float r = 0.0f;
#pragma unroll
            for (int j = 0; j < 4; ++j) {
                int xj = ix0 - 1 + j;
                if ((unsigned)xj < 128u) r = fmaf(wx[j], __ldg(rp + xj * Cn), r);
            }
            acc = fmaf(wy[i], r, acc);
        }
    }
    return acc;
}

// fp16 split + pack via packed cvt (v1 in high half, v0 in low half)
__device__ __forceinline__ void split_pack(float v0, float v1,
                                           uint32_t& hw, uint32_t& lw) {
    __half2 h = __floats2half2_rn(v0, v1);
    float2 f = __half22float2(h);
    __half2 l = __floats2half2_rn(v0 - f.x, v1 - f.y);
    hw = *reinterpret_cast<uint32_t*>(&h);
    lw = *reinterpret_cast<uint32_t*>(&l);
}

// ===========================================================================
// mma.sync m16n8k16 fp16
// ===========================================================================
__device__ __forceinline__ void mma_f16(float* c, const uint4& a,
                                        uint32_t b0, uint32_t b1) {
    asm("mma.sync.aligned.m16n8k16.row.col.f32.f16.f16.f32 "
        "{%0,%1,%2,%3},{%4,%5,%6,%7},{%8,%9},{%0,%1,%2,%3};"
        : "+f"(c[0]), "+f"(c[1]), "+f"(c[2]), "+f"(c[3])
        : "r"(a.x), "r"(a.y), "r"(a.z), "r"(a.w), "r"(b0), "r"(b1));
}

// Wide K-loop over BOTH 16-row blocks: C += Ah*B + Al*B.
template <int KC, int NC, int NPT>
__device__ __forceinline__ void mma_layer(const uint4* __restrict__ aHi,
                                          const uint4* __restrict__ aLo,
                                          const uint4* __restrict__ bHi,
                                          int nc0, float C[2][NC][4]) {
    const int lane = threadIdx.x & 31;
#pragma unroll
    for (int r = 0; r < 2; ++r)
#pragma unroll
        for (int j = 0; j < NC; ++j)
#pragma unroll
            for (int t = 0; t < 4; ++t) C[r][j][t] = 0.0f;
    const int npair0 = nc0 >> 1;
#pragma unroll 1
    for (int kc = 0; kc < KC; ++kc) {
        uint4 ah0 = aHi[(kc * NRB + 0) * 32 + lane];
        uint4 ah1 = aHi[(kc * NRB + 1) * 32 + lane];
        uint4 al0 = aLo[(kc * NRB + 0) * 32 + lane];
        uint4 al1 = aLo[(kc * NRB + 1) * 32 + lane];
#pragma unroll
        for (int p = 0; p < NC / 2; ++p) {
            uint4 bh = __ldg(bHi + (kc * NPT + npair0 + p) * 32 + lane);
            mma_f16(C[0][2 * p], ah0, bh.x, bh.y);
            mma_f16(C[1][2 * p], ah1, bh.x, bh.y);
            mma_f16(C[0][2 * p + 1], ah0, bh.z, bh.w);
            mma_f16(C[1][2 * p + 1], ah1, bh.z, bh.w);
            mma_f16(C[0][2 * p], al0, bh.x, bh.y);
            mma_f16(C[1][2 * p], al1, bh.x, bh.y);
            mma_f16(C[0][2 * p + 1], al0, bh.z, bh.w);
            mma_f16(C[1][2 * p + 1], al1, bh.z, bh.w);
        }
    }
}

// Partial K-slice for narrow (N<=32) layers: one npair, kc in [kc0, kc0+kcn).
__device__ __forceinline__ void mma_part(const uint4* __restrict__ aHi,
                                         const uint4* __restrict__ aLo,
                                         const uint4* __restrict__ bHi,
                                         int npair0, int kc0, int kcn, int NPT,
                                         float C[2][2][4]) {
    const int lane = threadIdx.x & 31;
#pragma unroll
    for (int r = 0; r < 2; ++r)
#pragma unroll
        for (int j = 0; j < 2; ++j)
#pragma unroll
            for (int t = 0; t < 4; ++t) C[r][j][t] = 0.0f;
#pragma unroll 1
    for (int kc = kc0; kc < kc0 + kcn; ++kc) {
        uint4 ah0 = aHi[(kc * NRB + 0) * 32 + lane];
        uint4 ah1 = aHi[(kc * NRB + 1) * 32 + lane];
        uint4 al0 = aLo[(kc * NRB + 0) * 32 + lane];
        uint4 al1 = aLo[(kc * NRB + 1) * 32 + lane];
        uint4 bh = __ldg(bHi + (kc * NPT + npair0) * 32 + lane);
        mma_f16(C[0][0], ah0, bh.x, bh.y);
        mma_f16(C[1][0], ah1, bh.x, bh.y);
        mma_f16(C[0][1], ah0, bh.z, bh.w);
        mma_f16(C[1][1], ah1, bh.z, bh.w);
        mma_f16(C[0][0], al0, bh.x, bh.y);
        mma_f16(C[1][0], al1, bh.x, bh.y);
        mma_f16(C[0][1], al0, bh.z, bh.w);
        mma_f16(C[1][1], al1, bh.z, bh.w);
    }
}

// Store a warp's narrow-layer partials to scratch (conflict-free float4 layout).
__device__ __forceinline__ void store_part(float4* scr4, int slice,
                                           float C[2][2][4]) {
    const int lane = threadIdx.x & 31;
#pragma unroll
    for (int r = 0; r < 2; ++r)
#pragma unroll
        for (int j = 0; j < 2; ++j) {
            int i = r * 2 + j;
            scr4[(i * 8 + slice) * 32 + lane] =
                make_float4(C[r][j][0], C[r][j][1], C[r][j][2], C[r][j][3]);
        }
}

// Reduce 4 k-slices (slices nh, nh+2, nh+4, nh+6) for n-half nh.
__device__ __forceinline__ void reduce4(const float4* scr4, int nh,
                                        float C[2][2][4]) {
    const int lane = threadIdx.x & 31;
#pragma unroll
    for (int i = 0; i < 4; ++i) {
        float4 a = scr4[(i * 8 + nh) * 32 + lane];
        float4 b = scr4[(i * 8 + 2 + nh) * 32 + lane];
        float4 c = scr4[(i * 8 + 4 + nh) * 32 + lane];
        float4 d = scr4[(i * 8 + 6 + nh) * 32 + lane];
        C[i >> 1][i & 1][0] = (a.x + b.x) + (c.x + d.x);
        C[i >> 1][i & 1][1] = (a.y + b.y) + (c.y + d.y);
        C[i >> 1][i & 1][2] = (a.z + b.z) + (c.z + d.z);
        C[i >> 1][i & 1][3] = (a.w + b.w) + (c.w + d.w);
    }
}

// Epilogue: bias(+ReLU), split to fp16 hi/lo A fragments for the next layer.
template <int NC, bool RELU>
__device__ __forceinline__ void epi_region(float C[2][NC][4],
                                           const float* __restrict__ biasp,
                                           int nc0,
                                           uint32_t* dHi, uint32_t* dLo) {
    const int lane = threadIdx.x & 31;
    const int q = (lane & 3) * 2;
#pragma unroll
    for (int j = 0; j < NC; ++j) {
        int nc = nc0 + j;
        int kc = nc >> 1, odd = nc & 1;
        float b0 = __ldg(biasp + nc * 8 + q);
        float b1 = __ldg(biasp + nc * 8 + q + 1);
#pragma unroll
        for (int r = 0; r < 2; ++r) {
            float v0 = C[r][j][0] + b0, v1 = C[r][j][1] + b1;
            float v2 = C[r][j][2] + b0, v3 = C[r][j][3] + b1;
            if (RELU) {
                v0 = fmaxf(v0, 0.f); v1 = fmaxf(v1, 0.f);
                v2 = fmaxf(v2, 0.f); v3 = fmaxf(v3, 0.f);
            }
            uint32_t h01, l01, h23, l23;
            split_pack(v0, v1, h01, l01);
            split_pack(v2, v3, h23, l23);
            int base = ((kc * NRB + r) * 32 + lane) * 4 + odd * 2;
            dHi[base] = h01; dHi[base + 1] = h23;
            dLo[base] = l01; dLo[base + 1] = l23;
        }
    }
}

// ===========================================================================
// SMEM layout (bytes) — total 53760; 3 CTAs/SM
// ===========================================================================
#define SM_INPF  0          // fp32 [32][49] = 6272 (reused as routs [32][33])
#define SM_SHI   6272       // inp frags hi: 3*2*512 = 3072
#define SM_SLO   9344
#define SM_PHI   12416      // pred frags hi: 2*2*512 = 2048
#define SM_PLO   14464
#define SM_AHI   16512      // act frags hi: 16*2*512 = 16384 (doubles as scratch)
#define SM_ALO   32896
#define SM_OFFS  49280      // fp32 [32][2] = 256
#define SM_OUT   49536      // fp32 [32][33] = 4224
#define SMEM_BYTES 53760

// ===========================================================================
// Fused kernel: 32 queries per CTA, 8 warps, 3 CTAs/SM.
// Wide layers: warp = unique 32 N-cols. Narrow layers: k-split over all warps.
// ===========================================================================
__global__ __launch_bounds__(256, 3) void fused_kernel(
    const float* __restrict__ b0p, const float* __restrict__ b1p,
    const float* __restrict__ b2p, const float* __restrict__ rb0p,
    const float* __restrict__ rb1p, const float* __restrict__ ob0p,
    const float* __restrict__ ob1p, float* __restrict__ out) {
    extern __shared__ __align__(16) unsigned char smraw[];
    float* inpF = reinterpret_cast<float*>(smraw + SM_INPF);
    uint4* SHi = reinterpret_cast<uint4*>(smraw + SM_SHI);
    uint4* SLo = reinterpret_cast<uint4*>(smraw + SM_SLO);
    uint4* PHi = reinterpret_cast<uint4*>(smraw + SM_PHI);
    uint4* PLo = reinterpret_cast<uint4*>(smraw + SM_PLO);
    uint4* AHi = reinterpret_cast<uint4*>(smraw + SM_AHI);
    uint4* ALo = reinterpret_cast<uint4*>(smraw + SM_ALO);
    uint32_t* PHiW = reinterpret_cast<uint32_t*>(PHi);
    uint32_t* PLoW = reinterpret_cast<uint32_t*>(PLo);
    uint32_t* AHiW = reinterpret_cast<uint32_t*>(AHi);
    uint32_t* ALoW = reinterpret_cast<uint32_t*>(ALo);
    float4* scr4 = reinterpret_cast<float4*>(smraw + SM_AHI);  // narrow-layer scratch
    float* offs  = reinterpret_cast<float*>(smraw + SM_OFFS);
    float* outst = reinterpret_cast<float*>(smraw + SM_OUT);
    float* routs = inpF;   // reuse after L1 staging

    const int tid = threadIdx.x;
    const int lane = tid & 31;
    const int wid = tid >> 5;

    const int q0 = blockIdx.x * MT;
    const int b = q0 >> 16;
    const int qbase = q0 & (QPB - 1);
    const float* xb = g_xt + b * (Hn * Wn * Cn);

    const uint4* WL1 = (const uint4*)(g_wimg + WOFF_L1);
    const uint4* WL2 = (const uint4*)(g_wimg + WOFF_L2);
    const uint4* WL3 = (const uint4*)(g_wimg + WOFF_L3);
    const uint4* WR0 = (const uint4*)(g_wimg + WOFF_R0);
    const uint4* WR1 = (const uint4*)(g_wimg + WOFF_R1);
    const uint4* WO0 = (const uint4*)(g_wimg + WOFF_O0);
    const uint4* WO1 = (const uint4*)(g_wimg + WOFF_O1);

    // ---- Stage A: sampling -> inpF [32][49] --------------------------------
#pragma unroll 1
    for (int i = 0; i < 4; ++i) {
        int m = wid * 4 + i;
        int ql = qbase + m;
        int oy = ql >> 8, ox = ql & 255;
        float gy = (2.0f * oy + 1.0f) * (1.0f / 256.0f) - 1.0f;
        float gx = (2.0f * ox + 1.0f) * (1.0f / 256.0f) - 1.0f;
        int ix0, iy0;
        float wx[4], wy[4];
        prep_axis(gx, ix0, wx);
        prep_axis(gy, iy0, wy);
        inpF[m * 49 + lane] = sample_c(xb, lane, ix0, iy0, wx, wy);
        if (lane == 0) {
            float syw = 0.f, sy = 0.f, sxw = 0.f, sx = 0.f;
#pragma unroll
            for (int ii = 0; ii < 4; ++ii) {
                int yi = iy0 - 1 + ii;
                if ((unsigned)yi < 128u) {
                    float yco = (2.0f * yi + 1.0f) * (1.0f / 128.0f) - 1.0f;
                    syw += wy[ii]; sy = fmaf(wy[ii], yco, sy);
                }
            }
#pragma unroll
            for (int jj = 0; jj < 4; ++jj) {
                int xj = ix0 - 1 + jj;
                if ((unsigned)xj < 128u) {
                    float xco = (2.0f * xj + 1.0f) * (1.0f / 128.0f) - 1.0f;
                    sxw += wx[jj]; sx = fmaf(wx[jj], xco, sx);
                }
            }
            inpF[m * 49 + 32] = (gy - sy * sxw) * 128.0f;
            inpF[m * 49 + 33] = (gx - sx * syw) * 128.0f;
            float rc = (ql < 2) ? 1.0f : 128.0f;   // faithful cell quirk
            inpF[m * 49 + 34] = rc;
            inpF[m * 49 + 35] = rc;
        }
        if (lane >= 4 && lane < 16) inpF[m * 49 + 32 + lane] = 0.0f;  // pad 36..47
    }
    __syncthreads();

    // ---- Stage S frags: inpF -> S (A-fragment fp16 hi/lo, K=48) -------------
    if (wid < 6) {
        int kc = wid >> 1, rbs = wid & 1;
        int r0 = rbs * 16 + (lane >> 2);
        int k0 = kc * 16 + (lane & 3) * 2;
        float v00 = inpF[r0 * 49 + k0],       v01 = inpF[r0 * 49 + k0 + 1];
        float v10 = inpF[(r0 + 8) * 49 + k0], v11 = inpF[(r0 + 8) * 49 + k0 + 1];
        float v02 = inpF[r0 * 49 + k0 + 8],   v03 = inpF[r0 * 49 + k0 + 9];
        float v12 = inpF[(r0 + 8) * 49 + k0 + 8], v13 = inpF[(r0 + 8) * 49 + k0 + 9];
        uint4 hi, lo;
        split_pack(v00, v01, hi.x, lo.x);
        split_pack(v10, v11, hi.y, lo.y);
        split_pack(v02, v03, hi.z, lo.z);
        split_pack(v12, v13, hi.w, lo.w);
        SHi[(kc * NRB + rbs) * 32 + lane] = hi;
        SLo[(kc * NRB + rbs) * 32 + lane] = lo;
    }
    __syncthreads();

    float C4[2][4][4];
    float C2[2][2][4];

    // ---- L1: S(K=48) x W0 -> h1 (N=256) -> A --------------------------------
    mma_layer<3, 4, 16>(SHi, SLo, WL1, wid * 4, C4);
    epi_region<4, true>(C4, b0p, wid * 4, AHiW, ALoW);
    __syncthreads();

    // ---- L2: A(K=256) x W1 -> h2 (N=256) -> A (in place) --------------------
    mma_layer<16, 4, 16>(AHi, ALo, WL2, wid * 4, C4);
    __syncthreads();
    epi_region<4, true>(C4, b1p, wid * 4, AHiW, ALoW);
    __syncthreads();

    // ---- L3 (k-split): A(K=256) x W2 -> pred (N=32) -> P --------------------
    mma_part(AHi, ALo, WL3, wid & 1, (wid >> 1) * 4, 4, 2, C2);
    __syncthreads();                     // all reads of A done
    store_part(scr4, wid, C2);
    __syncthreads();
    if (wid < 2) {
        reduce4(scr4, wid, C2);
        epi_region<2, false>(C2, b2p, wid * 2, PHiW, PLoW);
    }
    __syncthreads();

    // ---- O0: P(K=32) x OW0 -> off-hidden (N=256) -> A ------------------------
    mma_layer<2, 4, 16>(PHi, PLo, WO0, wid * 4, C4);
    epi_region<4, true>(C4, ob0p, wid * 4, AHiW, ALoW);
    __syncthreads();

    // ---- O1 (k-split): A(K=256) x OW1 -> offsets; R0 overlaps ----------------
    mma_part(AHi, ALo, WO1, 0, wid * 2, 2, 1, C2);
    __syncthreads();                     // all reads of A done
    store_part(scr4, wid, C2);
    __syncthreads();
    if (wid == 0) {
        // reduce 8 slices, nchunk 0 only (cols 0,1)
        float o[2][4];
#pragma unroll
        for (int ri = 0; ri < 2; ++ri) {
            int i = ri * 2;
            float4 acc = scr4[(i * 8 + 0) * 32 + lane];
#pragma unroll
            for (int s = 1; s < 8; ++s) {
                float4 v = scr4[(i * 8 + s) * 32 + lane];
                acc.x += v.x; acc.y += v.y; acc.z += v.z; acc.w += v.w;
            }
            o[ri][0] = acc.x; o[ri][1] = acc.y; o[ri][2] = acc.z; o[ri][3] = acc.w;
        }
        if ((lane & 3) == 0) {
            float o0 = __ldg(ob1p + 0), o1 = __ldg(ob1p + 1);
#pragma unroll
            for (int r = 0; r < 2; ++r) {
                int row = r * 16 + (lane >> 2);
                offs[row * 2 + 0] = o[r][0] + o0;
                offs[row * 2 + 1] = o[r][1] + o1;
                offs[(row + 8) * 2 + 0] = o[r][2] + o0;
                offs[(row + 8) * 2 + 1] = o[r][3] + o1;
            }
        }
    }
    // R0 mma overlaps with warp 0's reduction (reads only P-fragments)
    mma_layer<2, 4, 16>(PHi, PLo, WR0, wid * 4, C4);
    __syncthreads();                     // offs written; scratch consumed
    epi_region<4, true>(C4, rb0p, wid * 4, AHiW, ALoW);
    __syncthreads();

    // ---- R1 (k-split): A(K=256) x RW1 -> routing (N=32) -> routs fp32 --------
    mma_part(AHi, ALo, WR1, wid & 1, (wid >> 1) * 4, 4, 2, C2);
    __syncthreads();                     // all reads of A done
    store_part(scr4, wid, C2);
    __syncthreads();
    if (wid < 2) {
        reduce4(scr4, wid, C2);
        const int q = (lane & 3) * 2;
#pragma unroll
        for (int j = 0; j < 2; ++j) {
            int nc = wid * 2 + j;
            float bb0 = __ldg(rb1p + nc * 8 + q);
            float bb1 = __ldg(rb1p + nc * 8 + q + 1);
#pragma unroll
            for (int r = 0; r < 2; ++r) {
                int row = r * 16 + (lane >> 2);
                routs[row * 33 + nc * 8 + q]     = C2[r][j][0] + bb0;
                routs[row * 33 + nc * 8 + q + 1] = C2[r][j][1] + bb1;
                routs[(row + 8) * 33 + nc * 8 + q]     = C2[r][j][2] + bb0;
                routs[(row + 8) * 33 + nc * 8 + q + 1] = C2[r][j][3] + bb1;
            }
        }
    }
    __syncthreads();

    // ---- Stage C: offset resample + modulate ---------------------------------
#pragma unroll 1
    for (int i = 0; i < 4; ++i) {
        int m = wid * 4 + i;
        int ql = qbase + m;
        int oy = ql >> 8, ox = ql & 255;
        float gy = (2.0f * oy + 1.0f) * (1.0f / 256.0f) - 1.0f;
        float gx = (2.0f * ox + 1.0f) * (1.0f / 256.0f) - 1.0f;
        float gx2 = gx + offs[m * 2 + 0];
        float gy2 = gy + offs[m * 2 + 1];
        int ix0, iy0;
        float wx[4], wy[4];
        prep_axis(gx2, ix0, wx);
        prep_axis(gy2, iy0, wy);
        float v = sample_c(xb, lane, ix0, iy0, wx, wy);
        outst[lane * 33 + m] = v * (1.0f + routs[m * 33 + lane]);
    }
    __syncthreads();

    // ---- writeout -------------------------------------------------------------
    {
        int c = tid >> 3;
        int part = tid & 7;
        const float* src = outst + c * 33 + part * 4;
        float* dst = out + ((size_t)(b * Cn + c)) * QPB + qbase + part * 4;
        *reinterpret_cast<float4*>(dst) =
            make_float4(src[0], src[1], src[2], src[3]);
    }
}

// ===========================================================================
// kernel_launch — 2 launches: setup (xt + prep), fused
// ===========================================================================
extern "C" void kernel_launch(void* const* d_in, const int* in_sizes, int n_in,
                              void* d_out, int out_size) {
    const float* x   = (const float*)d_in[0];
    const float* w0  = (const float*)d_in[1];
    const float* b0  = (const float*)d_in[2];
    const float* w1  = (const float*)d_in[3];
    const float* b1  = (const float*)d_in[4];
    const float* w2  = (const float*)d_in[5];
    const float* b2  = (const float*)d_in[6];
    const float* rw0 = (const float*)d_in[7];
    const float* rb0 = (const float*)d_in[8];
    const float* rw1 = (const float*)d_in[9];
    const float* rb1 = (const float*)d_in[10];
    const float* ow0 = (const float*)d_in[11];
    const float* ob0 = (const float*)d_in[12];
    const float* ow1 = (const float*)d_in[13];
    const float* ob1 = (const float*)d_in[14];
    float* out = (float*)d_out;

    setup_kernel<<<dim3(512, 8), 256>>>(x, w0, w1, w2, rw0, rw1, ow0, ow1);

    cudaFuncSetAttribute(fused_kernel,
                         cudaFuncAttributeMaxDynamicSharedMemorySize, SMEM_BYTES);
    fused_kernel<<<NCTA, 256, SMEM_BYTES>>>(b0, b1, b2, rb0, rb1, ob0, ob1, out);
}

// round 11
// speedup vs baseline: 5.0916x; 1.2986x over previous
#include <cuda_runtime.h>
#include <cuda_fp16.h>
#include <cstdint>

// ===========================================================================
// Problem constants (fixed: B=4, C=32, H=W=128, scale=2)
// ===========================================================================
#define Bn    4
#define Cn    32
#define Hn    128
#define Wn    128
#define QPB   65536
#define NQ    (Bn * QPB)
#define MT    32                   // queries per CTA
#define NCTA  (NQ / MT)            // 8192
#define NRB   2                    // row-blocks (16 rows) per CTA

// ===========================================================================
// Global scratch
// ===========================================================================
__device__ float g_xt[Bn * Hn * Wn * Cn];   // channels-last x

// Weight images: B-fragment-packed fp16.
#define WOFF_L1  0u          // KC=3,  NPT=16 -> 24576
#define WOFF_L2  24576u      // KC=16, NPT=16 -> 131072
#define WOFF_L3  155648u     // KC=16, NPT=2  -> 16384
#define WOFF_R0  172032u     // KC=2,  NPT=16 -> 16384
#define WOFF_R1  188416u     // KC=16, NPT=2  -> 16384
#define WOFF_O0  204800u     // KC=2,  NPT=16 -> 16384
#define WOFF_O1  221184u     // KC=16, NPT=1  -> 8192
#define WIMG_TOTAL 229376u
__device__ __align__(16) unsigned char g_wimg[WIMG_TOTAL];

// ===========================================================================
// Setup kernel: y==0 -> transpose x; y>=1 -> weight prep for layer y-1.
// ===========================================================================
__global__ void setup_kernel(const float* __restrict__ x,
                             const float* __restrict__ w0, const float* __restrict__ w1,
                             const float* __restrict__ w2, const float* __restrict__ rw0,
                             const float* __restrict__ rw1, const float* __restrict__ ow0,
                             const float* __restrict__ ow1) {
    const int tid = threadIdx.x;
    if (blockIdx.y == 0) {
        __shared__ float s[Cn][Wn + 1];
        const int by = blockIdx.x;      // 0..511
#pragma unroll
        for (int it = 0; it < 16; ++it) {
            int idx = tid + it * 256;
            int c = idx >> 7, xc = idx & 127;
            int b = by >> 7, y = by & 127;
            s[c][xc] = x[((b * Cn + c) * Hn + y) * Wn + xc];
        }
        __syncthreads();
#pragma unroll
        for (int it = 0; it < 16; ++it) {
            int idx = tid + it * 256;
            int xc = idx >> 5, c = idx & 31;
            g_xt[(by * Wn + xc) * Cn + c] = s[c][xc];
        }
        return;
    }
    const float* W;
    int Kdim, Ndim, Kt, Nt;
    uint32_t dstOff;
    switch (blockIdx.y - 1) {
        case 0: W = w0;  Kdim = 36;  Ndim = 256; Kt = 48;  Nt = 256; dstOff = WOFF_L1; break;
        case 1: W = w1;  Kdim = 256; Ndim = 256; Kt = 256; Nt = 256; dstOff = WOFF_L2; break;
        case 2: W = w2;  Kdim = 256; Ndim = 32;  Kt = 256; Nt = 32;  dstOff = WOFF_L3; break;
        case 3: W = rw0; Kdim = 32;  Ndim = 256; Kt = 32;  Nt = 256; dstOff = WOFF_R0; break;
        case 4: W = rw1; Kdim = 256; Ndim = 32;  Kt = 256; Nt = 32;  dstOff = WOFF_R1; break;
        case 5: W = ow0; Kdim = 32;  Ndim = 256; Kt = 32;  Nt = 256; dstOff = WOFF_O0; break;
        default: W = ow1; Kdim = 256; Ndim = 2;  Kt = 256; Nt = 16;  dstOff = WOFF_O1; break;
    }
    int idx = blockIdx.x * 256 + tid;
    if (idx >= Kt * Nt) return;
    int k = idx / Nt;
    int n = idx % Nt;
    float w = (k < Kdim && n < Ndim) ? W[k * Ndim + n] : 0.0f;
    __half hb = __float2half_rn(w);
    int kc = k >> 4, ki = k & 15;
    int nc = n >> 3, ni = n & 7;
    int npair = nc >> 1;
    int lane = ni * 4 + ((ki & 7) >> 1);
    int word = (ki >> 3) + (nc & 1) * 2;
    int half = ki & 1;
    uint32_t off = (uint32_t)(((kc * (Nt >> 4) + npair) * 32 + lane) * 16 +
                              word * 4 + half * 2);
    *reinterpret_cast<unsigned short*>(g_wimg + dstOff + off) = __half_as_ushort(hb);
}

// ===========================================================================
// Bicubic helpers (torch aten, A=-0.75)
// ===========================================================================
__device__ __forceinline__ void prep_axis(float g, int& i0, float w[4]) {
    float p = ((g + 1.0f) * 128.0f - 1.0f) * 0.5f;
    float fp = floorf(p);
    i0 = (int)fp;
    float t = p - fp;
    const float A = -0.75f;
    float xx = t + 1.0f;
    w[0] = ((A * xx - 5.0f * A) * xx + 8.0f * A) * xx - 4.0f * A;
    w[1] = ((A + 2.0f) * t - (A + 3.0f)) * t * t + 1.0f;
    float s = 1.0f - t;
    w[2] = ((A + 2.0f) * s - (A + 3.0f)) * s * s + 1.0f;
    w[3] = 1.0f - w[0] - w[1] - w[2];
}

__device__ __forceinline__ float sample_c(const float* __restrict__ xb, int lane,
                                          int ix0, int iy0,
                                          const float* wx, const float* wy) {
    float acc = 0.0f;
#pragma unroll
    for (int i = 0; i < 4; ++i) {
        int yi = iy0 - 1 + i;
        if ((unsigned)yi < 128u) {
            const float* rp = xb + yi * (Wn * Cn) + lane;
            float r = 0.0f;
#pragma unroll
            for (int j = 0; j < 4; ++j) {
                int xj = ix0 - 1 + j;
                if ((unsigned)xj < 128u) r = fmaf(wx[j], __ldg(rp + xj * Cn), r);
            }
            acc = fmaf(wy[i], r, acc);
        }
    }
    return acc;
}

// packed fp16x2 (v1 in high half, v0 in low half)
__device__ __forceinline__ uint32_t pack_h2(float v0, float v1) {
    __half2 h = __floats2half2_rn(v0, v1);
    return *reinterpret_cast<uint32_t*>(&h);
}

// ===========================================================================
// mma.sync m16n8k16 fp16
// ===========================================================================
__device__ __forceinline__ void mma_f16(float* c, const uint4& a,
                                        uint32_t b0, uint32_t b1) {
    asm("mma.sync.aligned.m16n8k16.row.col.f32.f16.f16.f32 "
        "{%0,%1,%2,%3},{%4,%5,%6,%7},{%8,%9},{%0,%1,%2,%3};"
        : "+f"(c[0]), "+f"(c[1]), "+f"(c[2]), "+f"(c[3])
        : "r"(a.x), "r"(a.y), "r"(a.z), "r"(a.w), "r"(b0), "r"(b1));
}

// Wide K-loop over BOTH 16-row blocks, single-term: C += A*B.
template <int KC, int NC, int NPT>
__device__ __forceinline__ void mma_layer(const uint4* __restrict__ aHi,
                                          const uint4* __restrict__ bHi,
                                          int nc0, float C[2][NC][4]) {
    const int lane = threadIdx.x & 31;
#pragma unroll
    for (int r = 0; r < 2; ++r)
#pragma unroll
        for (int j = 0; j < NC; ++j)
#pragma unroll
            for (int t = 0; t < 4; ++t) C[r][j][t] = 0.0f;
    const int npair0 = nc0 >> 1;
#pragma unroll 1
    for (int kc = 0; kc < KC; ++kc) {
        uint4 ah0 = aHi[(kc * NRB + 0) * 32 + lane];
        uint4 ah1 = aHi[(kc * NRB + 1) * 32 + lane];
#pragma unroll
        for (int p = 0; p < NC / 2; ++p) {
            uint4 bh = __ldg(bHi + (kc * NPT + npair0 + p) * 32 + lane);
            mma_f16(C[0][2 * p], ah0, bh.x, bh.y);
            mma_f16(C[1][2 * p], ah1, bh.x, bh.y);
            mma_f16(C[0][2 * p + 1], ah0, bh.z, bh.w);
            mma_f16(C[1][2 * p + 1], ah1, bh.z, bh.w);
        }
    }
}

// Partial K-slice for narrow (N<=32) layers: one npair, kc in [kc0, kc0+kcn).
__device__ __forceinline__ void mma_part(const uint4* __restrict__ aHi,
                                         const uint4* __restrict__ bHi,
                                         int npair0, int kc0, int kcn, int NPT,
                                         float C[2][2][4]) {
    const int lane = threadIdx.x & 31;
#pragma unroll
    for (int r = 0; r < 2; ++r)
#pragma unroll
        for (int j = 0; j < 2; ++j)
#pragma unroll
            for (int t = 0; t < 4; ++t) C[r][j][t] = 0.0f;
#pragma unroll 1
    for (int kc = kc0; kc < kc0 + kcn; ++kc) {
        uint4 ah0 = aHi[(kc * NRB + 0) * 32 + lane];
        uint4 ah1 = aHi[(kc * NRB + 1) * 32 + lane];
        uint4 bh = __ldg(bHi + (kc * NPT + npair0) * 32 + lane);
        mma_f16(C[0][0], ah0, bh.x, bh.y);
        mma_f16(C[1][0], ah1, bh.x, bh.y);
        mma_f16(C[0][1], ah0, bh.z, bh.w);
        mma_f16(C[1][1], ah1, bh.z, bh.w);
    }
}

// Store a warp's narrow-layer partials to scratch (conflict-free float4 layout).
__device__ __forceinline__ void store_part(float4* scr4, int slice,
                                           float C[2][2][4]) {
    const int lane = threadIdx.x & 31;
#pragma unroll
    for (int r = 0; r < 2; ++r)
#pragma unroll
        for (int j = 0; j < 2; ++j) {
            int i = r * 2 + j;
            scr4[(i * 8 + slice) * 32 + lane] =
                make_float4(C[r][j][0], C[r][j][1], C[r][j][2], C[r][j][3]);
        }
}

// Reduce 4 k-slices (slices nh, nh+2, nh+4, nh+6) for n-half nh.
__device__ __forceinline__ void reduce4(const float4* scr4, int nh,
                                        float C[2][2][4]) {
    const int lane = threadIdx.x & 31;
#pragma unroll
    for (int i = 0; i < 4; ++i) {
        float4 a = scr4[(i * 8 + nh) * 32 + lane];
        float4 b = scr4[(i * 8 + 2 + nh) * 32 + lane];
        float4 c = scr4[(i * 8 + 4 + nh) * 32 + lane];
        float4 d = scr4[(i * 8 + 6 + nh) * 32 + lane];
        C[i >> 1][i & 1][0] = (a.x + b.x) + (c.x + d.x);
        C[i >> 1][i & 1][1] = (a.y + b.y) + (c.y + d.y);
        C[i >> 1][i & 1][2] = (a.z + b.z) + (c.z + d.z);
        C[i >> 1][i & 1][3] = (a.w + b.w) + (c.w + d.w);
    }
}

// Epilogue: bias(+ReLU), pack fp16 A fragments for the next layer (hi only).
template <int NC, bool RELU>
__device__ __forceinline__ void epi_region(float C[2][NC][4],
                                           const float* __restrict__ biasp,
                                           int nc0, uint32_t* dHi) {
    const int lane = threadIdx.x & 31;
    const int q = (lane & 3) * 2;
#pragma unroll
    for (int j = 0; j < NC; ++j) {
        int nc = nc0 + j;
        int kc = nc >> 1, odd = nc & 1;
        float b0 = __ldg(biasp + nc * 8 + q);
        float b1 = __ldg(biasp + nc * 8 + q + 1);
#pragma unroll
        for (int r = 0; r < 2; ++r) {
            float v0 = C[r][j][0] + b0, v1 = C[r][j][1] + b1;
            float v2 = C[r][j][2] + b0, v3 = C[r][j][3] + b1;
            if (RELU) {
                v0 = fmaxf(v0, 0.f); v1 = fmaxf(v1, 0.f);
                v2 = fmaxf(v2, 0.f); v3 = fmaxf(v3, 0.f);
            }
            int base = ((kc * NRB + r) * 32 + lane) * 4 + odd * 2;
            dHi[base] = pack_h2(v0, v1);
            dHi[base + 1] = pack_h2(v2, v3);
        }
    }
}

// ===========================================================================
// SMEM layout (bytes) — total 32256; 4 CTAs/SM
// ===========================================================================
#define SM_INPF  0          // fp32 [32][49] = 6272 (reused as routs [32][33])
#define SM_SHI   6272       // inp frags: 3*2*512 = 3072
#define SM_PHI   9344       // pred frags: 2*2*512 = 2048
#define SM_AHI   11392      // act frags: 16*2*512 = 16384 (doubles as scratch)
#define SM_OFFS  27776      // fp32 [32][2] = 256
#define SM_OUT   28032      // fp32 [32][33] = 4224
#define SMEM_BYTES 32256

// ===========================================================================
// Fused kernel: 32 queries per CTA, 8 warps, 4 CTAs/SM.
// Wide layers: warp = unique 32 N-cols. Narrow layers: k-split over all warps.
// ===========================================================================
__global__ __launch_bounds__(256, 4) void fused_kernel(
    const float* __restrict__ b0p, const float* __restrict__ b1p,
    const float* __restrict__ b2p, const float* __restrict__ rb0p,
    const float* __restrict__ rb1p, const float* __restrict__ ob0p,
    const float* __restrict__ ob1p, float* __restrict__ out) {
    extern __shared__ __align__(16) unsigned char smraw[];
    float* inpF = reinterpret_cast<float*>(smraw + SM_INPF);
    uint4* SHi = reinterpret_cast<uint4*>(smraw + SM_SHI);
    uint4* PHi = reinterpret_cast<uint4*>(smraw + SM_PHI);
    uint4* AHi = reinterpret_cast<uint4*>(smraw + SM_AHI);
    uint32_t* PHiW = reinterpret_cast<uint32_t*>(PHi);
    uint32_t* AHiW = reinterpret_cast<uint32_t*>(AHi);
    float4* scr4 = reinterpret_cast<float4*>(smraw + SM_AHI);  // narrow-layer scratch
    float* offs  = reinterpret_cast<float*>(smraw + SM_OFFS);
    float* outst = reinterpret_cast<float*>(smraw + SM_OUT);
    float* routs = inpF;   // reuse after L1 staging

    const int tid = threadIdx.x;
    const int lane = tid & 31;
    const int wid = tid >> 5;

    const int q0 = blockIdx.x * MT;
    const int b = q0 >> 16;
    const int qbase = q0 & (QPB - 1);
    const float* xb = g_xt + b * (Hn * Wn * Cn);

    const uint4* WL1 = (const uint4*)(g_wimg + WOFF_L1);
    const uint4* WL2 = (const uint4*)(g_wimg + WOFF_L2);
    const uint4* WL3 = (const uint4*)(g_wimg + WOFF_L3);
    const uint4* WR0 = (const uint4*)(g_wimg + WOFF_R0);
    const uint4* WR1 = (const uint4*)(g_wimg + WOFF_R1);
    const uint4* WO0 = (const uint4*)(g_wimg + WOFF_O0);
    const uint4* WO1 = (const uint4*)(g_wimg + WOFF_O1);

    // ---- Stage A: sampling -> inpF [32][49] --------------------------------
#pragma unroll 1
    for (int i = 0; i < 4; ++i) {
        int m = wid * 4 + i;
        int ql = qbase + m;
        int oy = ql >> 8, ox = ql & 255;
        float gy = (2.0f * oy + 1.0f) * (1.0f / 256.0f) - 1.0f;
        float gx = (2.0f * ox + 1.0f) * (1.0f / 256.0f) - 1.0f;
        int ix0, iy0;
        float wx[4], wy[4];
        prep_axis(gx, ix0, wx);
        prep_axis(gy, iy0, wy);
        inpF[m * 49 + lane] = sample_c(xb, lane, ix0, iy0, wx, wy);
        if (lane == 0) {
            float syw = 0.f, sy = 0.f, sxw = 0.f, sx = 0.f;
#pragma unroll
            for (int ii = 0; ii < 4; ++ii) {
                int yi = iy0 - 1 + ii;
                if ((unsigned)yi < 128u) {
                    float yco = (2.0f * yi + 1.0f) * (1.0f / 128.0f) - 1.0f;
                    syw += wy[ii]; sy = fmaf(wy[ii], yco, sy);
                }
            }
#pragma unroll
            for (int jj = 0; jj < 4; ++jj) {
                int xj = ix0 - 1 + jj;
                if ((unsigned)xj < 128u) {
                    float xco = (2.0f * xj + 1.0f) * (1.0f / 128.0f) - 1.0f;
                    sxw += wx[jj]; sx = fmaf(wx[jj], xco, sx);
                }
            }
            inpF[m * 49 + 32] = (gy - sy * sxw) * 128.0f;
            inpF[m * 49 + 33] = (gx - sx * syw) * 128.0f;
            float rc = (ql < 2) ? 1.0f : 128.0f;   // faithful cell quirk
            inpF[m * 49 + 34] = rc;
            inpF[m * 49 + 35] = rc;
        }
        if (lane >= 4 && lane < 16) inpF[m * 49 + 32 + lane] = 0.0f;  // pad 36..47
    }
    __syncthreads();

    // ---- Stage S frags: inpF -> S (A-fragment fp16, K=48) -------------------
    if (wid < 6) {
        int kc = wid >> 1, rbs = wid & 1;
        int r0 = rbs * 16 + (lane >> 2);
        int k0 = kc * 16 + (lane & 3) * 2;
        uint4 hi;
        hi.x = pack_h2(inpF[r0 * 49 + k0], inpF[r0 * 49 + k0 + 1]);
        hi.y = pack_h2(inpF[(r0 + 8) * 49 + k0], inpF[(r0 + 8) * 49 + k0 + 1]);
        hi.z = pack_h2(inpF[r0 * 49 + k0 + 8], inpF[r0 * 49 + k0 + 9]);
        hi.w = pack_h2(inpF[(r0 + 8) * 49 + k0 + 8], inpF[(r0 + 8) * 49 + k0 + 9]);
        SHi[(kc * NRB + rbs) * 32 + lane] = hi;
    }
    __syncthreads();

    float C4[2][4][4];
    float C2[2][2][4];

    // ---- L1: S(K=48) x W0 -> h1 (N=256) -> A --------------------------------
    mma_layer<3, 4, 16>(SHi, WL1, wid * 4, C4);
    epi_region<4, true>(C4, b0p, wid * 4, AHiW);
    __syncthreads();

    // ---- L2: A(K=256) x W1 -> h2 (N=256) -> A (in place) --------------------
    mma_layer<16, 4, 16>(AHi, WL2, wid * 4, C4);
    __syncthreads();
    epi_region<4, true>(C4, b1p, wid * 4, AHiW);
    __syncthreads();

    // ---- L3 (k-split): A(K=256) x W2 -> pred (N=32) -> P --------------------
    mma_part(AHi, WL3, wid & 1, (wid >> 1) * 4, 4, 2, C2);
    __syncthreads();                     // all reads of A done
    store_part(scr4, wid, C2);
    __syncthreads();
    if (wid < 2) {
        reduce4(scr4, wid, C2);
        epi_region<2, false>(C2, b2p, wid * 2, PHiW);
    }
    __syncthreads();

    // ---- O0: P(K=32) x OW0 -> off-hidden (N=256) -> A ------------------------
    mma_layer<2, 4, 16>(PHi, WO0, wid * 4, C4);
    epi_region<4, true>(C4, ob0p, wid * 4, AHiW);
    __syncthreads();

    // ---- O1 (k-split): A(K=256) x OW1 -> offsets; R0 overlaps ----------------
    mma_part(AHi, WO1, 0, wid * 2, 2, 1, C2);
    __syncthreads();                     // all reads of A done
    store_part(scr4, wid, C2);
    __syncthreads();
    if (wid == 0) {
        float o[2][4];
#pragma unroll
        for (int ri = 0; ri < 2; ++ri) {
            int i = ri * 2;
            float4 acc = scr4[(i * 8 + 0) * 32 + lane];
#pragma unroll
            for (int s = 1; s < 8; ++s) {
                float4 v = scr4[(i * 8 + s) * 32 + lane];
                acc.x += v.x; acc.y += v.y; acc.z += v.z; acc.w += v.w;
            }
            o[ri][0] = acc.x; o[ri][1] = acc.y; o[ri][2] = acc.z; o[ri][3] = acc.w;
        }
        if ((lane & 3) == 0) {
            float o0 = __ldg(ob1p + 0), o1 = __ldg(ob1p + 1);
#pragma unroll
            for (int r = 0; r < 2; ++r) {
                int row = r * 16 + (lane >> 2);
                offs[row * 2 + 0] = o[r][0] + o0;
                offs[row * 2 + 1] = o[r][1] + o1;
                offs[(row + 8) * 2 + 0] = o[r][2] + o0;
                offs[(row + 8) * 2 + 1] = o[r][3] + o1;
            }
        }
    }
    // R0 mma overlaps with warp 0's reduction (reads only P-fragments)
    mma_layer<2, 4, 16>(PHi, WR0, wid * 4, C4);
    __syncthreads();                     // offs written; scratch consumed
    epi_region<4, true>(C4, rb0p, wid * 4, AHiW);
    __syncthreads();

    // ---- R1 (k-split): A(K=256) x RW1 -> routing (N=32) -> routs fp32 --------
    mma_part(AHi, WR1, wid & 1, (wid >> 1) * 4, 4, 2, C2);
    __syncthreads();                     // all reads of A done
    store_part(scr4, wid, C2);
    __syncthreads();
    if (wid < 2) {
        reduce4(scr4, wid, C2);
        const int q = (lane & 3) * 2;
#pragma unroll
        for (int j = 0; j < 2; ++j) {
            int nc = wid * 2 + j;
            float bb0 = __ldg(rb1p + nc * 8 + q);
            float bb1 = __ldg(rb1p + nc * 8 + q + 1);
#pragma unroll
            for (int r = 0; r < 2; ++r) {
                int row = r * 16 + (lane >> 2);
                routs[row * 33 + nc * 8 + q]     = C2[r][j][0] + bb0;
                routs[row * 33 + nc * 8 + q + 1] = C2[r][j][1] + bb1;
                routs[(row + 8) * 33 + nc * 8 + q]     = C2[r][j][2] + bb0;
                routs[(row + 8) * 33 + nc * 8 + q + 1] = C2[r][j][3] + bb1;
            }
        }
    }
    __syncthreads();

    // ---- Stage C: offset resample + modulate ---------------------------------
#pragma unroll 1
    for (int i = 0; i < 4; ++i) {
        int m = wid * 4 + i;
        int ql = qbase + m;
        int oy = ql >> 8, ox = ql & 255;
        float gy = (2.0f * oy + 1.0f) * (1.0f / 256.0f) - 1.0f;
        float gx = (2.0f * ox + 1.0f) * (1.0f / 256.0f) - 1.0f;
        float gx2 = gx + offs[m * 2 + 0];
        float gy2 = gy + offs[m * 2 + 1];
        int ix0, iy0;
        float wx[4], wy[4];
        prep_axis(gx2, ix0, wx);
        prep_axis(gy2, iy0, wy);
        float v = sample_c(xb, lane, ix0, iy0, wx, wy);
        outst[lane * 33 + m] = v * (1.0f + routs[m * 33 + lane]);
    }
    __syncthreads();

    // ---- writeout -------------------------------------------------------------
    {
        int c = tid >> 3;
        int part = tid & 7;
        const float* src = outst + c * 33 + part * 4;
        float* dst = out + ((size_t)(b * Cn + c)) * QPB + qbase + part * 4;
        *reinterpret_cast<float4*>(dst) =
            make_float4(src[0], src[1], src[2], src[3]);
    }
}

// ===========================================================================
// kernel_launch — 2 launches: setup (xt + prep), fused
// ===========================================================================
extern "C" void kernel_launch(void* const* d_in, const int* in_sizes, int n_in,
                              void* d_out, int out_size) {
    const float* x   = (const float*)d_in[0];
    const float* w0  = (const float*)d_in[1];
    const float* b0  = (const float*)d_in[2];
    const float* w1  = (const float*)d_in[3];
    const float* b1  = (const float*)d_in[4];
    const float* w2  = (const float*)d_in[5];
    const float* b2  = (const float*)d_in[6];
    const float* rw0 = (const float*)d_in[7];
    const float* rb0 = (const float*)d_in[8];
    const float* rw1 = (const float*)d_in[9];
    const float* rb1 = (const float*)d_in[10];
    const float* ow0 = (const float*)d_in[11];
    const float* ob0 = (const float*)d_in[12];
    const float* ow1 = (const float*)d_in[13];
    const float* ob1 = (const float*)d_in[14];
    float* out = (float*)d_out;

    setup_kernel<<<dim3(512, 8), 256>>>(x, w0, w1, w2, rw0, rw1, ow0, ow1);

    cudaFuncSetAttribute(fused_kernel,
                         cudaFuncAttributeMaxDynamicSharedMemorySize, SMEM_BYTES);
    fused_kernel<<<NCTA, 256, SMEM_BYTES>>>(b0, b1, b2, rb0, rb1, ob0, ob1, out);
}